// round 8
// baseline (speedup 1.0000x reference)
#include <cuda_runtime.h>
#include <cuda_bf16.h>
#include <cstdint>
#include <math.h>

#define TOK   8192
#define E     1024
#define H3    3072
#define MLPD  4096
#define NHEAD 16
#define HDIM  64
#define SEQ   2048

// ---------------------------------------------------------------------------
// Scratch: all intermediate activations stored as split bf16 pairs (hi/lo)
// ---------------------------------------------------------------------------
__device__ uint16_t g_h_hi   [(size_t)TOK * E];
__device__ uint16_t g_h_lo   [(size_t)TOK * E];
__device__ uint16_t g_qkv_hi [(size_t)TOK * H3];
__device__ uint16_t g_qkv_lo [(size_t)TOK * H3];
__device__ uint16_t g_attn_hi[(size_t)TOK * E];
__device__ uint16_t g_attn_lo[(size_t)TOK * E];
__device__ float    g_x1     [(size_t)TOK * E];
__device__ uint16_t g_mlp_hi [(size_t)TOK * MLPD];
__device__ uint16_t g_mlp_lo [(size_t)TOK * MLPD];
__device__ uint16_t g_wq_hi  [(size_t)H3 * E];
__device__ uint16_t g_wq_lo  [(size_t)H3 * E];
__device__ uint16_t g_wf_hi  [(size_t)E * E];
__device__ uint16_t g_wf_lo  [(size_t)E * E];
__device__ uint16_t g_w1_hi  [(size_t)MLPD * E];
__device__ uint16_t g_w1_lo  [(size_t)MLPD * E];
__device__ uint16_t g_w2_hi  [(size_t)E * MLPD];
__device__ uint16_t g_w2_lo  [(size_t)E * MLPD];

__device__ __forceinline__ uint32_t smem_u32(const void* p) {
    uint32_t a;
    asm("{ .reg .u64 t; cvta.to.shared.u64 t, %1; cvt.u32.u64 %0, t; }"
        : "=r"(a) : "l"(p));
    return a;
}

#define LDSM_X4(r, addr) \
    asm volatile("ldmatrix.sync.aligned.m8n8.x4.shared.b16 {%0,%1,%2,%3}, [%4];" \
        : "=r"((r)[0]), "=r"((r)[1]), "=r"((r)[2]), "=r"((r)[3]) : "r"(addr))

#define LDSM_X4_T(r, addr) \
    asm volatile("ldmatrix.sync.aligned.m8n8.x4.trans.shared.b16 {%0,%1,%2,%3}, [%4];" \
        : "=r"((r)[0]), "=r"((r)[1]), "=r"((r)[2]), "=r"((r)[3]) : "r"(addr))

__device__ __forceinline__ void mma_bf16(float* c, const uint32_t* a, const uint32_t* b) {
    asm volatile(
        "mma.sync.aligned.m16n8k16.row.col.f32.bf16.bf16.f32 "
        "{%0,%1,%2,%3}, {%4,%5,%6,%7}, {%8,%9}, {%0,%1,%2,%3};"
        : "+f"(c[0]), "+f"(c[1]), "+f"(c[2]), "+f"(c[3])
        : "r"(a[0]), "r"(a[1]), "r"(a[2]), "r"(a[3]), "r"(b[0]), "r"(b[1]));
}

__device__ __forceinline__ void split_pack(float c0, float c1,
                                           uint32_t& hi, uint32_t& lo)
{
    uint32_t u0 = __float_as_uint(c0), u1 = __float_as_uint(c1);
    hi = (u1 & 0xffff0000u) | (u0 >> 16);
    float l0 = c0 - __uint_as_float(u0 & 0xffff0000u);
    float l1 = c1 - __uint_as_float(u1 & 0xffff0000u);
    asm("cvt.rn.bf16x2.f32 %0, %1, %2;" : "=r"(lo) : "f"(l1), "f"(l0));
}

__device__ __forceinline__ float ex2(float x) {
    float r;
    asm("ex2.approx.f32 %0, %1;" : "=f"(r) : "f"(x));
    return r;
}

__device__ __forceinline__ void cpa16(uint32_t dst, const void* src) {
    asm volatile("cp.async.cg.shared.global [%0], [%1], 16;"
                 :: "r"(dst), "l"(src));
}
#define CP_COMMIT() asm volatile("cp.async.commit_group;" ::: "memory")
#define CP_WAIT0()  asm volatile("cp.async.wait_group 0;" ::: "memory")

__device__ __forceinline__ void cvt_sts(float4 v, char* hi, char* lo, uint32_t off)
{
    uint32_t h01, h23, l01, l23;
    split_pack(v.x, v.y, h01, l01);
    split_pack(v.z, v.w, h23, l23);
    *(uint2*)(hi + off) = make_uint2(h01, h23);
    *(uint2*)(lo + off) = make_uint2(l01, l23);
}

// ---------------------------------------------------------------------------
// Weight pre-split: fp32 -> hi/lo bf16 arrays
// ---------------------------------------------------------------------------
__global__ void wconv(const float* __restrict__ src, uint16_t* __restrict__ hi,
                      uint16_t* __restrict__ lo, int n4)
{
    int i = blockIdx.x * 256 + threadIdx.x;
    if (i < n4) {
        float4 v = ((const float4*)src)[i];
        uint32_t h01, l01, h23, l23;
        split_pack(v.x, v.y, h01, l01);
        split_pack(v.z, v.w, h23, l23);
        ((uint2*)hi)[i] = make_uint2(h01, h23);
        ((uint2*)lo)[i] = make_uint2(l01, l23);
    }
}

// ---------------------------------------------------------------------------
// LayerNorm: fp32 in -> split bf16 pair out
// ---------------------------------------------------------------------------
__global__ void ln_kernel(const float* __restrict__ x,
                          const float* __restrict__ g,
                          const float* __restrict__ b,
                          uint16_t* __restrict__ yhi,
                          uint16_t* __restrict__ ylo)
{
    int row = blockIdx.x;
    int tid = threadIdx.x;
    const float4* xr = (const float4*)(x + (size_t)row * E);
    float4 v = xr[tid];

    float s  = v.x + v.y + v.z + v.w;
    float ss = v.x * v.x + v.y * v.y + v.z * v.z + v.w * v.w;

    __shared__ float sbuf[32], sbuf2[32];
    #pragma unroll
    for (int o = 16; o > 0; o >>= 1) {
        s  += __shfl_down_sync(0xffffffffu, s,  o);
        ss += __shfl_down_sync(0xffffffffu, ss, o);
    }
    int warp = tid >> 5, lane = tid & 31;
    if (lane == 0) { sbuf[warp] = s; sbuf2[warp] = ss; }
    __syncthreads();
    if (warp == 0) {
        s  = lane < 8 ? sbuf[lane]  : 0.f;
        ss = lane < 8 ? sbuf2[lane] : 0.f;
        #pragma unroll
        for (int o = 4; o > 0; o >>= 1) {
            s  += __shfl_down_sync(0xffffffffu, s,  o);
            ss += __shfl_down_sync(0xffffffffu, ss, o);
        }
        if (lane == 0) { sbuf[0] = s; sbuf2[0] = ss; }
    }
    __syncthreads();
    float mean = sbuf[0] * (1.0f / E);
    float var  = sbuf2[0] * (1.0f / E) - mean * mean;
    float rstd = rsqrtf(var + 1e-5f);

    float4 gv = ((const float4*)g)[tid];
    float4 bv = ((const float4*)b)[tid];
    float o0 = (v.x - mean) * rstd * gv.x + bv.x;
    float o1 = (v.y - mean) * rstd * gv.y + bv.y;
    float o2 = (v.z - mean) * rstd * gv.z + bv.z;
    float o3 = (v.w - mean) * rstd * gv.w + bv.w;
    uint32_t h01, l01, h23, l23;
    split_pack(o0, o1, h01, l01);
    split_pack(o2, o3, h23, l23);
    size_t base = (size_t)row * E + tid * 4;
    *(uint2*)(yhi + base) = make_uint2(h01, h23);
    *(uint2*)(ylo + base) = make_uint2(l01, l23);
}

// ---------------------------------------------------------------------------
// Split-bf16 mma.sync NT GEMM with cp.async pipeline.
// ---------------------------------------------------------------------------
#define SROW   80
#define MATB   10240
#define STAGEB 40960
#define GEMM_SMEM (2 * STAGEB)

__device__ __forceinline__ void gemm_issue(uint32_t stg,
    const uint16_t* __restrict__ Ahi, const uint16_t* __restrict__ Alo,
    const uint16_t* __restrict__ Bhi, const uint16_t* __restrict__ Blo,
    int K, int k0, int tid)
{
    #pragma unroll
    for (int i = 0; i < 2; i++) {
        int c = tid * 2 + i;                 // 0..511
        int r = c >> 2, kc = c & 3;
        uint32_t doff = (uint32_t)(r * SROW + kc * 16);
        size_t soff = (size_t)r * K + k0 + kc * 8;
        cpa16(stg + doff,            Ahi + soff);
        cpa16(stg + MATB + doff,     Alo + soff);
        cpa16(stg + 2 * MATB + doff, Bhi + soff);
        cpa16(stg + 3 * MATB + doff, Blo + soff);
    }
    CP_COMMIT();
}

__global__ __launch_bounds__(256)
void gemm_mma(const uint16_t* __restrict__ Ahi, const uint16_t* __restrict__ Alo,
              const uint16_t* __restrict__ Bhi, const uint16_t* __restrict__ Blo,
              const float* __restrict__ bias, const float* __restrict__ res,
              float* __restrict__ outf,
              uint16_t* __restrict__ ohi, uint16_t* __restrict__ olo,
              int M, int N, int K, int act)
{
    extern __shared__ char sm[];
    uint32_t sb = smem_u32(sm);
    int tid = threadIdx.x, w = tid >> 5, lane = tid & 31;
    int wm = w >> 2, wn = w & 3;
    int bn = blockIdx.x, bm = blockIdx.y;

    const uint16_t* Abh = Ahi + (size_t)bm * 128 * K;
    const uint16_t* Abl = Alo + (size_t)bm * 128 * K;
    const uint16_t* Bbh = Bhi + (size_t)bn * 128 * K;
    const uint16_t* Bbl = Blo + (size_t)bn * 128 * K;
    int nch = K >> 5;

    float acc[4][4][4];
    #pragma unroll
    for (int i = 0; i < 4; i++)
        #pragma unroll
        for (int j = 0; j < 4; j++)
            #pragma unroll
            for (int c = 0; c < 4; c++) acc[i][j][c] = 0.f;

    gemm_issue(sb, Abh, Abl, Bbh, Bbl, K, 0, tid);
    CP_WAIT0();
    __syncthreads();

    uint32_t a_row = (uint32_t)(wm * 64 + (lane & 15)) * SROW + ((lane >> 4) * 8) * 2;
    uint32_t b_row = (uint32_t)(wn * 32 + (lane & 7) + ((lane >> 4) & 1) * 8) * SROW
                   + (((lane >> 3) & 1) * 8) * 2;

    for (int k = 0; k < nch; k++) {
        if (k + 1 < nch)
            gemm_issue(sb + (uint32_t)((k + 1) & 1) * STAGEB,
                       Abh, Abl, Bbh, Bbl, K, (k + 1) * 32, tid);

        uint32_t stg = sb + (uint32_t)(k & 1) * STAGEB;
        #pragma unroll
        for (int ks = 0; ks < 2; ks++) {
            uint32_t koff = (uint32_t)(ks * 32);
            uint32_t ah[4][4], al[4][4], bh[2][4], bl[2][4];
            #pragma unroll
            for (int mf = 0; mf < 4; mf++) {
                uint32_t addr = stg + a_row + (uint32_t)(mf * 16) * SROW + koff;
                LDSM_X4(ah[mf], addr);
                LDSM_X4(al[mf], addr + MATB);
            }
            #pragma unroll
            for (int np = 0; np < 2; np++) {
                uint32_t addr = stg + 2 * MATB + b_row + (uint32_t)(np * 16) * SROW + koff;
                LDSM_X4(bh[np], addr);
                LDSM_X4(bl[np], addr + MATB);
            }
            #pragma unroll
            for (int mf = 0; mf < 4; mf++)
                #pragma unroll
                for (int nf = 0; nf < 4; nf++) {
                    const uint32_t* bhf = &bh[nf >> 1][(nf & 1) * 2];
                    const uint32_t* blf = &bl[nf >> 1][(nf & 1) * 2];
                    mma_bf16(acc[mf][nf], ah[mf], bhf);
                    mma_bf16(acc[mf][nf], ah[mf], blf);
                    mma_bf16(acc[mf][nf], al[mf], bhf);
                }
        }
        CP_WAIT0();
        __syncthreads();
    }

    int g = lane >> 2, tig = lane & 3;
    #pragma unroll
    for (int mf = 0; mf < 4; mf++) {
        #pragma unroll
        for (int h2 = 0; h2 < 2; h2++) {
            int row = bm * 128 + wm * 64 + mf * 16 + g + h2 * 8;
            size_t rb = (size_t)row * N;
            #pragma unroll
            for (int nf = 0; nf < 4; nf++) {
                int col = bn * 128 + wn * 32 + nf * 8 + tig * 2;
                float v0 = acc[mf][nf][h2 * 2 + 0];
                float v1 = acc[mf][nf][h2 * 2 + 1];
                if (bias) {
                    float2 bv = *(const float2*)(bias + col);
                    v0 += bv.x; v1 += bv.y;
                }
                if (act == 1) {
                    v0 = 0.5f * v0 * (1.0f + erff(v0 * 0.70710678118654752f));
                    v1 = 0.5f * v1 * (1.0f + erff(v1 * 0.70710678118654752f));
                }
                if (res) {
                    float2 rv = *(const float2*)(res + rb + col);
                    v0 += rv.x; v1 += rv.y;
                }
                if (outf)
                    *(float2*)(outf + rb + col) = make_float2(v0, v1);
                if (ohi) {
                    uint32_t hp, lp;
                    split_pack(v0, v1, hp, lp);
                    *(uint32_t*)(ohi + rb + col) = hp;
                    *(uint32_t*)(olo + rb + col) = lp;
                }
            }
        }
    }
}

// ---------------------------------------------------------------------------
// Tensor-core flash attention, pair inputs/outputs, cp.async KV pipeline.
// ---------------------------------------------------------------------------
#define AROW 144
#define Q_HI 0
#define Q_LO 18432
#define KV0  36864
#define KVSTG 36864
#define ATTN_SMEM (KV0 + 2 * KVSTG)
#define QSCALE 0.18033688011112042f   // 0.125 * log2(e)

__device__ __forceinline__ void attn_issue(uint32_t stg,
    const uint16_t* __restrict__ qhi, const uint16_t* __restrict__ qlo,
    int b, int h, int kt, int tid)
{
    #pragma unroll
    for (int i = 0; i < 2; i++) {
        int c = tid * 2 + i;                  // 0..511
        int rr = c >> 3, kc = c & 7;
        size_t base = (size_t)(b * SEQ + kt * 64 + rr) * H3 + h * HDIM + kc * 8;
        uint32_t doff = (uint32_t)(rr * AROW + kc * 16);
        cpa16(stg + doff,          qhi + base + E);
        cpa16(stg + 9216 + doff,   qlo + base + E);
        cpa16(stg + 18432 + doff,  qhi + base + 2 * E);
        cpa16(stg + 27648 + doff,  qlo + base + 2 * E);
    }
    CP_COMMIT();
}

__global__ __launch_bounds__(256)
void attn_mma(const uint16_t* __restrict__ qhi, const uint16_t* __restrict__ qlo,
              uint16_t* __restrict__ ohi_g, uint16_t* __restrict__ olo_g)
{
    extern __shared__ char sm[];
    uint32_t sb = smem_u32(sm);
    int qt = blockIdx.x, h = blockIdx.y, b = blockIdx.z;
    int tid = threadIdx.x, w = tid >> 5, lane = tid & 31;
    int g = lane >> 2, tig = lane & 3;

    // issue KV tile 0 async, then convert Q while it flies
    attn_issue(sb + KV0, qhi, qlo, b, h, 0, tid);

    // Q tile: 128 rows x 64 d = 2048 float4-chunks -> 8 iterations of 256 thr
    #pragma unroll
    for (int i = 0; i < 8; i++) {
        int idx = i * 256 + tid;
        int r = idx >> 4, c4 = idx & 15;
        size_t t = (size_t)(b * SEQ + qt * 128 + r) * H3 + h * HDIM + c4 * 4;
        uint2 hh = *(const uint2*)(qhi + t);
        uint2 ll = *(const uint2*)(qlo + t);
        float4 v;
        v.x = (__uint_as_float(hh.x << 16) + __uint_as_float(ll.x << 16)) * QSCALE;
        v.y = (__uint_as_float(hh.x & 0xffff0000u) + __uint_as_float(ll.x & 0xffff0000u)) * QSCALE;
        v.z = (__uint_as_float(hh.y << 16) + __uint_as_float(ll.y << 16)) * QSCALE;
        v.w = (__uint_as_float(hh.y & 0xffff0000u) + __uint_as_float(ll.y & 0xffff0000u)) * QSCALE;
        cvt_sts(v, sm + Q_HI, sm + Q_LO, (uint32_t)(r * AROW + c4 * 8));
    }
    CP_WAIT0();
    __syncthreads();

    // preload Q fragments
    uint32_t qh[4][4], ql[4][4];
    {
        uint32_t qa = sb + Q_HI + (uint32_t)(w * 16 + (lane & 15)) * AROW
                    + ((lane >> 4) * 8) * 2;
        #pragma unroll
        for (int ks = 0; ks < 4; ks++) {
            LDSM_X4(qh[ks], qa + (uint32_t)(ks * 32));
            LDSM_X4(ql[ks], qa + (uint32_t)(ks * 32) + Q_LO);
        }
    }

    float o[8][4];
    #pragma unroll
    for (int nf = 0; nf < 8; nf++)
        #pragma unroll
        for (int c = 0; c < 4; c++) o[nf][c] = 0.f;
    float m_[2] = {-1e30f, -1e30f};
    float l_[2] = {0.f, 0.f};

    uint32_t kb_off = (uint32_t)((lane & 7) + ((lane >> 4) & 1) * 8) * AROW
                    + (((lane >> 3) & 1) * 8) * 2;
    uint32_t vb_off = (uint32_t)(lane & 15) * AROW + ((lane >> 4) * 8) * 2 + 18432;

    for (int kt = 0; kt < SEQ / 64; kt++) {
        uint32_t stg = sb + KV0 + (uint32_t)(kt & 1) * KVSTG;

        if (kt + 1 < SEQ / 64)
            attn_issue(sb + KV0 + (uint32_t)((kt + 1) & 1) * KVSTG,
                       qhi, qlo, b, h, kt + 1, tid);

        // ---- S = Q K^T ----
        float s[8][4];
        #pragma unroll
        for (int nf = 0; nf < 8; nf++)
            #pragma unroll
            for (int c = 0; c < 4; c++) s[nf][c] = 0.f;

        #pragma unroll
        for (int ks = 0; ks < 4; ks++) {
            uint32_t koff = (uint32_t)(ks * 32);
            #pragma unroll
            for (int ng = 0; ng < 4; ng++) {
                uint32_t addr = stg + kb_off + (uint32_t)(ng * 16) * AROW + koff;
                uint32_t kh[4], kl[4];
                LDSM_X4(kh, addr);
                LDSM_X4(kl, addr + 9216);
                #pragma unroll
                for (int j = 0; j < 2; j++) {
                    int nf = ng * 2 + j;
                    mma_bf16(s[nf], qh[ks], &kh[j * 2]);
                    mma_bf16(s[nf], qh[ks], &kl[j * 2]);
                    mma_bf16(s[nf], ql[ks], &kh[j * 2]);
                }
            }
        }

        // ---- online softmax (base 2) ----
        #pragma unroll
        for (int hh = 0; hh < 2; hh++) {
            float mx = s[0][hh * 2];
            #pragma unroll
            for (int nf = 0; nf < 8; nf++) {
                mx = fmaxf(mx, s[nf][hh * 2 + 0]);
                mx = fmaxf(mx, s[nf][hh * 2 + 1]);
            }
            mx = fmaxf(mx, __shfl_xor_sync(0xffffffffu, mx, 1));
            mx = fmaxf(mx, __shfl_xor_sync(0xffffffffu, mx, 2));
            float mn = fmaxf(m_[hh], mx);
            float alpha = ex2(m_[hh] - mn);
            m_[hh] = mn;
            float lsum = 0.f;
            #pragma unroll
            for (int nf = 0; nf < 8; nf++) {
                float p0 = ex2(s[nf][hh * 2 + 0] - mn);
                float p1 = ex2(s[nf][hh * 2 + 1] - mn);
                s[nf][hh * 2 + 0] = p0;
                s[nf][hh * 2 + 1] = p1;
                lsum += p0 + p1;
                o[nf][hh * 2 + 0] *= alpha;
                o[nf][hh * 2 + 1] *= alpha;
            }
            l_[hh] = l_[hh] * alpha + lsum;
        }

        // ---- O += P V ----
        #pragma unroll
        for (int ks = 0; ks < 4; ks++) {
            uint32_t ph[4], pl[4];
            split_pack(s[ks*2  ][0], s[ks*2  ][1], ph[0], pl[0]);
            split_pack(s[ks*2  ][2], s[ks*2  ][3], ph[1], pl[1]);
            split_pack(s[ks*2+1][0], s[ks*2+1][1], ph[2], pl[2]);
            split_pack(s[ks*2+1][2], s[ks*2+1][3], ph[3], pl[3]);
            #pragma unroll
            for (int nd = 0; nd < 4; nd++) {
                uint32_t addr = stg + vb_off + (uint32_t)(ks * 16) * AROW
                              + (uint32_t)(nd * 16) * 2;
                uint32_t vh[4], vl[4];
                LDSM_X4_T(vh, addr);
                LDSM_X4_T(vl, addr + 9216);
                #pragma unroll
                for (int j = 0; j < 2; j++) {
                    int nf = nd * 2 + j;
                    mma_bf16(o[nf], ph, &vh[j * 2]);
                    mma_bf16(o[nf], ph, &vl[j * 2]);
                    mma_bf16(o[nf], pl, &vh[j * 2]);
                }
            }
        }

        CP_WAIT0();
        __syncthreads();
    }

    // ---- finalize: write pair output ----
    #pragma unroll
    for (int hh = 0; hh < 2; hh++) {
        float lt = l_[hh];
        lt += __shfl_xor_sync(0xffffffffu, lt, 1);
        lt += __shfl_xor_sync(0xffffffffu, lt, 2);
        float inv = 1.0f / lt;
        int row = qt * 128 + w * 16 + g + hh * 8;
        size_t base = (size_t)(b * SEQ + row) * E + h * HDIM;
        #pragma unroll
        for (int nf = 0; nf < 8; nf++) {
            int col = nf * 8 + tig * 2;
            uint32_t hp, lp;
            split_pack(o[nf][hh * 2 + 0] * inv, o[nf][hh * 2 + 1] * inv, hp, lp);
            *(uint32_t*)(ohi_g + base + col) = hp;
            *(uint32_t*)(olo_g + base + col) = lp;
        }
    }
}

// ---------------------------------------------------------------------------
// Launch
// ---------------------------------------------------------------------------
extern "C" void kernel_launch(void* const* d_in, const int* in_sizes, int n_in,
                              void* d_out, int out_size)
{
    const float* x     = (const float*)d_in[0];
    const float* qkv_w = (const float*)d_in[1];
    const float* fc_w  = (const float*)d_in[2];
    const float* fc_b  = (const float*)d_in[3];
    const float* ln1_g = (const float*)d_in[4];
    const float* ln1_b = (const float*)d_in[5];
    const float* ln2_g = (const float*)d_in[6];
    const float* ln2_b = (const float*)d_in[7];
    const float* w1    = (const float*)d_in[8];
    const float* b1    = (const float*)d_in[9];
    const float* w2    = (const float*)d_in[10];
    const float* b2    = (const float*)d_in[11];
    float* out = (float*)d_out;

    uint16_t *phh, *phl, *pqh, *pql, *pah, *pal, *pmh, *pml;
    uint16_t *wqh, *wql, *wfh, *wfl, *w1h, *w1l, *w2h, *w2l;
    float* px1;
    cudaGetSymbolAddress((void**)&phh, g_h_hi);
    cudaGetSymbolAddress((void**)&phl, g_h_lo);
    cudaGetSymbolAddress((void**)&pqh, g_qkv_hi);
    cudaGetSymbolAddress((void**)&pql, g_qkv_lo);
    cudaGetSymbolAddress((void**)&pah, g_attn_hi);
    cudaGetSymbolAddress((void**)&pal, g_attn_lo);
    cudaGetSymbolAddress((void**)&pmh, g_mlp_hi);
    cudaGetSymbolAddress((void**)&pml, g_mlp_lo);
    cudaGetSymbolAddress((void**)&px1, g_x1);
    cudaGetSymbolAddress((void**)&wqh, g_wq_hi);
    cudaGetSymbolAddress((void**)&wql, g_wq_lo);
    cudaGetSymbolAddress((void**)&wfh, g_wf_hi);
    cudaGetSymbolAddress((void**)&wfl, g_wf_lo);
    cudaGetSymbolAddress((void**)&w1h, g_w1_hi);
    cudaGetSymbolAddress((void**)&w1l, g_w1_lo);
    cudaGetSymbolAddress((void**)&w2h, g_w2_hi);
    cudaGetSymbolAddress((void**)&w2l, g_w2_lo);

    cudaFuncSetAttribute(gemm_mma, cudaFuncAttributeMaxDynamicSharedMemorySize,
                         GEMM_SMEM);
    cudaFuncSetAttribute(attn_mma, cudaFuncAttributeMaxDynamicSharedMemorySize,
                         ATTN_SMEM);

    // weight pre-split
    wconv<<<(H3 * E / 4 + 255) / 256, 256>>>(qkv_w, wqh, wql, H3 * E / 4);
    wconv<<<(E * E / 4 + 255) / 256, 256>>>(fc_w, wfh, wfl, E * E / 4);
    wconv<<<(MLPD * E / 4 + 255) / 256, 256>>>(w1, w1h, w1l, MLPD * E / 4);
    wconv<<<(E * MLPD / 4 + 255) / 256, 256>>>(w2, w2h, w2l, E * MLPD / 4);

    // 1. h = LN1(x) -> pair
    ln_kernel<<<TOK, 256>>>(x, ln1_g, ln1_b, phh, phl);
    // 2. qkv = h @ qkv_w^T -> pair
    gemm_mma<<<dim3(H3 / 128, TOK / 128), 256, GEMM_SMEM>>>(
        phh, phl, wqh, wql, nullptr, nullptr, nullptr, pqh, pql,
        TOK, H3, E, 0);
    // 3. attention -> pair
    attn_mma<<<dim3(SEQ / 128, NHEAD, 4), 256, ATTN_SMEM>>>(pqh, pql, pah, pal);
    // 4. x1 = x + attn @ fc_w^T + fc_b -> fp32
    gemm_mma<<<dim3(E / 128, TOK / 128), 256, GEMM_SMEM>>>(
        pah, pal, wfh, wfl, fc_b, x, px1, nullptr, nullptr,
        TOK, E, E, 0);
    // 5. h = LN2(x1) -> pair
    ln_kernel<<<TOK, 256>>>(px1, ln2_g, ln2_b, phh, phl);
    // 6. mlp = gelu(h @ w1^T + b1) -> pair
    gemm_mma<<<dim3(MLPD / 128, TOK / 128), 256, GEMM_SMEM>>>(
        phh, phl, w1h, w1l, b1, nullptr, nullptr, pmh, pml,
        TOK, MLPD, E, 1);
    // 7. out = x1 + mlp @ w2^T + b2 -> fp32
    gemm_mma<<<dim3(E / 128, TOK / 128), 256, GEMM_SMEM>>>(
        pmh, pml, w2h, w2l, b2, px1, out, nullptr, nullptr,
        TOK, E, MLPD, 0);
}

// round 9
// speedup vs baseline: 1.6201x; 1.6201x over previous
#include <cuda_runtime.h>
#include <cuda_fp16.h>
#include <cstdint>
#include <math.h>

#define TOK   8192
#define E     1024
#define H3    3072
#define MLPD  4096
#define NHEAD 16
#define HDIM  64
#define SEQ   2048

// ---------------------------------------------------------------------------
// Scratch (fp32 activations, R6 layout)
// ---------------------------------------------------------------------------
__device__ float g_h   [(size_t)TOK * E];
__device__ float g_qkv [(size_t)TOK * H3];
__device__ float g_attn[(size_t)TOK * E];
__device__ float g_x1  [(size_t)TOK * E];
__device__ float g_mlp [(size_t)TOK * MLPD];

__device__ __forceinline__ uint32_t smem_u32(const void* p) {
    uint32_t a;
    asm("{ .reg .u64 t; cvta.to.shared.u64 t, %1; cvt.u32.u64 %0, t; }"
        : "=r"(a) : "l"(p));
    return a;
}

#define LDSM_X4(r, addr) \
    asm volatile("ldmatrix.sync.aligned.m8n8.x4.shared.b16 {%0,%1,%2,%3}, [%4];" \
        : "=r"((r)[0]), "=r"((r)[1]), "=r"((r)[2]), "=r"((r)[3]) : "r"(addr))

#define LDSM_X4_T(r, addr) \
    asm volatile("ldmatrix.sync.aligned.m8n8.x4.trans.shared.b16 {%0,%1,%2,%3}, [%4];" \
        : "=r"((r)[0]), "=r"((r)[1]), "=r"((r)[2]), "=r"((r)[3]) : "r"(addr))

__device__ __forceinline__ void mma_f16(float* c, const uint32_t* a, const uint32_t* b) {
    asm volatile(
        "mma.sync.aligned.m16n8k16.row.col.f32.f16.f16.f32 "
        "{%0,%1,%2,%3}, {%4,%5,%6,%7}, {%8,%9}, {%0,%1,%2,%3};"
        : "+f"(c[0]), "+f"(c[1]), "+f"(c[2]), "+f"(c[3])
        : "r"(a[0]), "r"(a[1]), "r"(a[2]), "r"(a[3]), "r"(b[0]), "r"(b[1]));
}

// fp32 pair -> packed fp16 hi + fp16 lo (lo = rn(x - hi))
__device__ __forceinline__ void split_pack(float c0, float c1,
                                           uint32_t& hi, uint32_t& lo)
{
    asm("cvt.rn.f16x2.f32 %0, %1, %2;" : "=r"(hi) : "f"(c1), "f"(c0));
    __half2 h2 = *reinterpret_cast<__half2*>(&hi);
    float l0 = c0 - __low2float(h2);
    float l1 = c1 - __high2float(h2);
    asm("cvt.rn.f16x2.f32 %0, %1, %2;" : "=r"(lo) : "f"(l1), "f"(l0));
}

__device__ __forceinline__ uint32_t pack_f16(float c0, float c1) {
    uint32_t h;
    asm("cvt.rn.f16x2.f32 %0, %1, %2;" : "=r"(h) : "f"(c1), "f"(c0));
    return h;
}

__device__ __forceinline__ float ex2(float x) {
    float r;
    asm("ex2.approx.f32 %0, %1;" : "=f"(r) : "f"(x));
    return r;
}

// smem stores
__device__ __forceinline__ void cvt_sts_pair(float4 v, char* hi, char* lo, uint32_t off)
{
    uint32_t h01, h23, l01, l23;
    split_pack(v.x, v.y, h01, l01);
    split_pack(v.z, v.w, h23, l23);
    *(uint2*)(hi + off) = make_uint2(h01, h23);
    *(uint2*)(lo + off) = make_uint2(l01, l23);
}
__device__ __forceinline__ void cvt_sts_hi(float4 v, char* hi, uint32_t off)
{
    *(uint2*)(hi + off) = make_uint2(pack_f16(v.x, v.y), pack_f16(v.z, v.w));
}

// ---------------------------------------------------------------------------
// LayerNorm (fp32 -> fp32)
// ---------------------------------------------------------------------------
__global__ void ln_kernel(const float* __restrict__ x,
                          const float* __restrict__ g,
                          const float* __restrict__ b,
                          float* __restrict__ y)
{
    int row = blockIdx.x;
    int tid = threadIdx.x;
    const float4* xr = (const float4*)(x + (size_t)row * E);
    float4 v = xr[tid];

    float s  = v.x + v.y + v.z + v.w;
    float ss = v.x * v.x + v.y * v.y + v.z * v.z + v.w * v.w;

    __shared__ float sbuf[32], sbuf2[32];
    #pragma unroll
    for (int o = 16; o > 0; o >>= 1) {
        s  += __shfl_down_sync(0xffffffffu, s,  o);
        ss += __shfl_down_sync(0xffffffffu, ss, o);
    }
    int warp = tid >> 5, lane = tid & 31;
    if (lane == 0) { sbuf[warp] = s; sbuf2[warp] = ss; }
    __syncthreads();
    if (warp == 0) {
        s  = lane < 8 ? sbuf[lane]  : 0.f;
        ss = lane < 8 ? sbuf2[lane] : 0.f;
        #pragma unroll
        for (int o = 4; o > 0; o >>= 1) {
            s  += __shfl_down_sync(0xffffffffu, s,  o);
            ss += __shfl_down_sync(0xffffffffu, ss, o);
        }
        if (lane == 0) { sbuf[0] = s; sbuf2[0] = ss; }
    }
    __syncthreads();
    float mean = sbuf[0] * (1.0f / E);
    float var  = sbuf2[0] * (1.0f / E) - mean * mean;
    float rstd = rsqrtf(var + 1e-5f);

    float4 gv = ((const float4*)g)[tid];
    float4 bv = ((const float4*)b)[tid];
    float4 o;
    o.x = (v.x - mean) * rstd * gv.x + bv.x;
    o.y = (v.y - mean) * rstd * gv.y + bv.y;
    o.z = (v.z - mean) * rstd * gv.z + bv.z;
    o.w = (v.w - mean) * rstd * gv.w + bv.w;
    ((float4*)(y + (size_t)row * E))[tid] = o;
}

// ---------------------------------------------------------------------------
// Split-fp16 mma.sync NT GEMM: C = act(A @ B^T + bias) + res
// A split (hi+lo), B hi-only. CTA 128x128, BK=32, 8 warps (64x32 each).
// smem stage (30720 B): Ahi(10240) Alo(10240) Bhi(10240), row stride 80 B.
// ---------------------------------------------------------------------------
#define SROW   80
#define MATB   10240
#define STAGEB 30720
#define GEMM_SMEM (2 * STAGEB)

struct StageRegs { float4 a[4]; float4 b[4]; };

__device__ __forceinline__ void ldg_stage(StageRegs& s,
                                          const float* __restrict__ Ab,
                                          const float* __restrict__ Bb,
                                          int K, int k0, int tid)
{
    #pragma unroll
    for (int i = 0; i < 4; i++) {
        int idx = i * 256 + tid;
        int r = idx >> 3, c4 = idx & 7;
        s.a[i] = *(const float4*)(Ab + (size_t)r * K + k0 + c4 * 4);
        s.b[i] = *(const float4*)(Bb + (size_t)r * K + k0 + c4 * 4);
    }
}

__device__ __forceinline__ void sts_stage(const StageRegs& s, char* stg, int tid)
{
    #pragma unroll
    for (int i = 0; i < 4; i++) {
        int idx = i * 256 + tid;
        int r = idx >> 3, c4 = idx & 7;
        uint32_t off = (uint32_t)(r * SROW + c4 * 8);
        cvt_sts_pair(s.a[i], stg, stg + MATB, off);
        cvt_sts_hi(s.b[i], stg + 2 * MATB, off);
    }
}

__global__ __launch_bounds__(256)
void gemm_mma(const float* __restrict__ A, const float* __restrict__ B,
              const float* __restrict__ bias, const float* __restrict__ res,
              float* __restrict__ C, int M, int N, int K, int act)
{
    extern __shared__ char sm[];
    uint32_t sb = smem_u32(sm);
    int tid = threadIdx.x, w = tid >> 5, lane = tid & 31;
    int wm = w >> 2, wn = w & 3;
    int bn = blockIdx.x, bm = blockIdx.y;

    const float* Ab = A + (size_t)bm * 128 * K;
    const float* Bb = B + (size_t)bn * 128 * K;
    int nch = K >> 5;

    float acc[4][4][4];
    #pragma unroll
    for (int i = 0; i < 4; i++)
        #pragma unroll
        for (int j = 0; j < 4; j++)
            #pragma unroll
            for (int c = 0; c < 4; c++) acc[i][j][c] = 0.f;

    StageRegs st;
    ldg_stage(st, Ab, Bb, K, 0, tid);
    sts_stage(st, sm, tid);
    __syncthreads();

    uint32_t a_row = (uint32_t)(wm * 64 + (lane & 15)) * SROW + ((lane >> 4) * 8) * 2;
    uint32_t b_row = (uint32_t)(wn * 32 + (lane & 7) + ((lane >> 4) & 1) * 8) * SROW
                   + (((lane >> 3) & 1) * 8) * 2;

    for (int k = 0; k < nch; k++) {
        StageRegs nxt;
        if (k + 1 < nch) ldg_stage(nxt, Ab, Bb, K, (k + 1) * 32, tid);

        uint32_t stg = sb + (uint32_t)(k & 1) * STAGEB;
        #pragma unroll
        for (int ks = 0; ks < 2; ks++) {
            uint32_t koff = (uint32_t)(ks * 32);
            uint32_t ah[4][4], al[4][4], bh[2][4];
            #pragma unroll
            for (int mf = 0; mf < 4; mf++) {
                uint32_t addr = stg + a_row + (uint32_t)(mf * 16) * SROW + koff;
                LDSM_X4(ah[mf], addr);
                LDSM_X4(al[mf], addr + MATB);
            }
            #pragma unroll
            for (int np = 0; np < 2; np++) {
                uint32_t addr = stg + 2 * MATB + b_row + (uint32_t)(np * 16) * SROW + koff;
                LDSM_X4(bh[np], addr);
            }
            #pragma unroll
            for (int mf = 0; mf < 4; mf++)
                #pragma unroll
                for (int nf = 0; nf < 4; nf++) {
                    const uint32_t* bhf = &bh[nf >> 1][(nf & 1) * 2];
                    mma_f16(acc[mf][nf], ah[mf], bhf);
                    mma_f16(acc[mf][nf], al[mf], bhf);
                }
        }
        if (k + 1 < nch) sts_stage(nxt, sm + ((k + 1) & 1) * STAGEB, tid);
        __syncthreads();
    }

    int g = lane >> 2, tig = lane & 3;
    #pragma unroll
    for (int mf = 0; mf < 4; mf++) {
        #pragma unroll
        for (int h2 = 0; h2 < 2; h2++) {
            int row = bm * 128 + wm * 64 + mf * 16 + g + h2 * 8;
            float* Crow = C + (size_t)row * N;
            const float* Rrow = res ? res + (size_t)row * N : (const float*)0;
            #pragma unroll
            for (int nf = 0; nf < 4; nf++) {
                int col = bn * 128 + wn * 32 + nf * 8 + tig * 2;
                float v0 = acc[mf][nf][h2 * 2 + 0];
                float v1 = acc[mf][nf][h2 * 2 + 1];
                if (bias) {
                    float2 bv = *(const float2*)(bias + col);
                    v0 += bv.x; v1 += bv.y;
                }
                if (act == 1) {
                    v0 = 0.5f * v0 * (1.0f + erff(v0 * 0.70710678118654752f));
                    v1 = 0.5f * v1 * (1.0f + erff(v1 * 0.70710678118654752f));
                }
                if (Rrow) {
                    float2 rv = *(const float2*)(Rrow + col);
                    v0 += rv.x; v1 += rv.y;
                }
                *(float2*)(Crow + col) = make_float2(v0, v1);
            }
        }
    }
}

// ---------------------------------------------------------------------------
// Tensor-core flash attention (fp16): Q split pair, K/V hi-only.
// CTA: 128 Q rows x (head,batch). 256 threads. KV tiles 64, double-buffered.
// smem: Q_HI(18432) Q_LO(18432), then 2 stages of [K(9216) V(9216)].
// ---------------------------------------------------------------------------
#define AROW 144
#define Q_HI 0
#define Q_LO 18432
#define KV0  36864
#define KVSTG 18432
#define ATTN_SMEM (KV0 + 2 * KVSTG)
#define QSCALE 0.18033688011112042f   // 0.125 * log2(e)

struct KVregs { float4 k[4]; float4 v[4]; };

__device__ __forceinline__ void ldg_kv(KVregs& r, const float* __restrict__ qkv,
                                       int b, int h, int kt, int tid)
{
    #pragma unroll
    for (int i = 0; i < 4; i++) {
        int idx = i * 256 + tid;
        int rr = idx >> 4, c4 = idx & 15;
        size_t base = (size_t)(b * SEQ + kt * 64 + rr) * H3 + h * HDIM + c4 * 4;
        r.k[i] = *(const float4*)(qkv + base + E);
        r.v[i] = *(const float4*)(qkv + base + 2 * E);
    }
}

__device__ __forceinline__ void sts_kv(const KVregs& r, char* stg, int tid)
{
    #pragma unroll
    for (int i = 0; i < 4; i++) {
        int idx = i * 256 + tid;
        int rr = idx >> 4, c4 = idx & 15;
        uint32_t off = (uint32_t)(rr * AROW + c4 * 8);
        cvt_sts_hi(r.k[i], stg, off);
        cvt_sts_hi(r.v[i], stg + 9216, off);
    }
}

__global__ __launch_bounds__(256)
void attn_mma(const float* __restrict__ qkv, float* __restrict__ out)
{
    extern __shared__ char sm[];
    uint32_t sb = smem_u32(sm);
    int qt = blockIdx.x, h = blockIdx.y, b = blockIdx.z;
    int tid = threadIdx.x, w = tid >> 5, lane = tid & 31;
    int g = lane >> 2, tig = lane & 3;

    // load Q tile (scaled), split pair
    #pragma unroll
    for (int i = 0; i < 8; i++) {
        int idx = i * 256 + tid;
        int r = idx >> 4, c4 = idx & 15;
        size_t token = (size_t)(b * SEQ + qt * 128 + r);
        float4 v = *(const float4*)(qkv + token * H3 + h * HDIM + c4 * 4);
        v.x *= QSCALE; v.y *= QSCALE; v.z *= QSCALE; v.w *= QSCALE;
        cvt_sts_pair(v, sm + Q_HI, sm + Q_LO, (uint32_t)(r * AROW + c4 * 8));
    }

    // KV tile 0
    {
        KVregs r0;
        ldg_kv(r0, qkv, b, h, 0, tid);
        sts_kv(r0, sm + KV0, tid);
    }
    __syncthreads();

    // preload Q fragments (this warp's 16 rows, 4 k-steps)
    uint32_t qh[4][4], ql[4][4];
    {
        uint32_t qa = sb + Q_HI + (uint32_t)(w * 16 + (lane & 15)) * AROW
                    + ((lane >> 4) * 8) * 2;
        #pragma unroll
        for (int ks = 0; ks < 4; ks++) {
            LDSM_X4(qh[ks], qa + (uint32_t)(ks * 32));
            LDSM_X4(ql[ks], qa + (uint32_t)(ks * 32) + Q_LO);
        }
    }

    float o[8][4];
    #pragma unroll
    for (int nf = 0; nf < 8; nf++)
        #pragma unroll
        for (int c = 0; c < 4; c++) o[nf][c] = 0.f;
    float m_[2] = {-1e30f, -1e30f};
    float l_[2] = {0.f, 0.f};

    uint32_t kb_off = (uint32_t)((lane & 7) + ((lane >> 4) & 1) * 8) * AROW
                    + (((lane >> 3) & 1) * 8) * 2;
    uint32_t vb_off = (uint32_t)(lane & 15) * AROW + ((lane >> 4) * 8) * 2 + 9216;

    for (int kt = 0; kt < SEQ / 64; kt++) {
        uint32_t stg = sb + KV0 + (uint32_t)(kt & 1) * KVSTG;

        KVregs nxt;
        if (kt + 1 < SEQ / 64) ldg_kv(nxt, qkv, b, h, kt + 1, tid);

        // ---- S = Q K^T (2-MMA split) ----
        float s[8][4];
        #pragma unroll
        for (int nf = 0; nf < 8; nf++)
            #pragma unroll
            for (int c = 0; c < 4; c++) s[nf][c] = 0.f;

        #pragma unroll
        for (int ks = 0; ks < 4; ks++) {
            uint32_t koff = (uint32_t)(ks * 32);
            #pragma unroll
            for (int ng = 0; ng < 4; ng++) {
                uint32_t addr = stg + kb_off + (uint32_t)(ng * 16) * AROW + koff;
                uint32_t kh[4];
                LDSM_X4(kh, addr);
                #pragma unroll
                for (int j = 0; j < 2; j++) {
                    int nf = ng * 2 + j;
                    mma_f16(s[nf], qh[ks], &kh[j * 2]);
                    mma_f16(s[nf], ql[ks], &kh[j * 2]);
                }
            }
        }

        // ---- online softmax (base 2) ----
        #pragma unroll
        for (int hh = 0; hh < 2; hh++) {
            float mx = s[0][hh * 2];
            #pragma unroll
            for (int nf = 0; nf < 8; nf++) {
                mx = fmaxf(mx, s[nf][hh * 2 + 0]);
                mx = fmaxf(mx, s[nf][hh * 2 + 1]);
            }
            mx = fmaxf(mx, __shfl_xor_sync(0xffffffffu, mx, 1));
            mx = fmaxf(mx, __shfl_xor_sync(0xffffffffu, mx, 2));
            float mn = fmaxf(m_[hh], mx);
            float alpha = ex2(m_[hh] - mn);
            m_[hh] = mn;
            float lsum = 0.f;
            #pragma unroll
            for (int nf = 0; nf < 8; nf++) {
                float p0 = ex2(s[nf][hh * 2 + 0] - mn);
                float p1 = ex2(s[nf][hh * 2 + 1] - mn);
                s[nf][hh * 2 + 0] = p0;
                s[nf][hh * 2 + 1] = p1;
                lsum += p0 + p1;
                o[nf][hh * 2 + 0] *= alpha;
                o[nf][hh * 2 + 1] *= alpha;
            }
            l_[hh] = l_[hh] * alpha + lsum;
        }

        // ---- O += P V (P split pair, V hi-only) ----
        #pragma unroll
        for (int ks = 0; ks < 4; ks++) {
            uint32_t ph[4], pl[4];
            split_pack(s[ks*2  ][0], s[ks*2  ][1], ph[0], pl[0]);
            split_pack(s[ks*2  ][2], s[ks*2  ][3], ph[1], pl[1]);
            split_pack(s[ks*2+1][0], s[ks*2+1][1], ph[2], pl[2]);
            split_pack(s[ks*2+1][2], s[ks*2+1][3], ph[3], pl[3]);
            #pragma unroll
            for (int nd = 0; nd < 4; nd++) {
                uint32_t addr = stg + vb_off + (uint32_t)(ks * 16) * AROW
                              + (uint32_t)(nd * 16) * 2;
                uint32_t vh[4];
                LDSM_X4_T(vh, addr);
                #pragma unroll
                for (int j = 0; j < 2; j++) {
                    int nf = nd * 2 + j;
                    mma_f16(o[nf], ph, &vh[j * 2]);
                    mma_f16(o[nf], pl, &vh[j * 2]);
                }
            }
        }

        if (kt + 1 < SEQ / 64)
            sts_kv(nxt, sm + KV0 + ((kt + 1) & 1) * KVSTG, tid);
        __syncthreads();
    }

    // ---- finalize ----
    #pragma unroll
    for (int hh = 0; hh < 2; hh++) {
        float lt = l_[hh];
        lt += __shfl_xor_sync(0xffffffffu, lt, 1);
        lt += __shfl_xor_sync(0xffffffffu, lt, 2);
        float inv = 1.0f / lt;
        int row = qt * 128 + w * 16 + g + hh * 8;
        size_t token = (size_t)(b * SEQ + row);
        float* op = out + token * E + h * HDIM;
        #pragma unroll
        for (int nf = 0; nf < 8; nf++) {
            int col = nf * 8 + tig * 2;
            *(float2*)(op + col) = make_float2(o[nf][hh * 2 + 0] * inv,
                                               o[nf][hh * 2 + 1] * inv);
        }
    }
}

// ---------------------------------------------------------------------------
// Launch
// ---------------------------------------------------------------------------
extern "C" void kernel_launch(void* const* d_in, const int* in_sizes, int n_in,
                              void* d_out, int out_size)
{
    const float* x     = (const float*)d_in[0];
    const float* qkv_w = (const float*)d_in[1];
    const float* fc_w  = (const float*)d_in[2];
    const float* fc_b  = (const float*)d_in[3];
    const float* ln1_g = (const float*)d_in[4];
    const float* ln1_b = (const float*)d_in[5];
    const float* ln2_g = (const float*)d_in[6];
    const float* ln2_b = (const float*)d_in[7];
    const float* w1    = (const float*)d_in[8];
    const float* b1    = (const float*)d_in[9];
    const float* w2    = (const float*)d_in[10];
    const float* b2    = (const float*)d_in[11];
    float* out = (float*)d_out;

    float *ph, *pqkv, *pattn, *px1, *pmlp;
    cudaGetSymbolAddress((void**)&ph,    g_h);
    cudaGetSymbolAddress((void**)&pqkv,  g_qkv);
    cudaGetSymbolAddress((void**)&pattn, g_attn);
    cudaGetSymbolAddress((void**)&px1,   g_x1);
    cudaGetSymbolAddress((void**)&pmlp,  g_mlp);

    cudaFuncSetAttribute(gemm_mma, cudaFuncAttributeMaxDynamicSharedMemorySize,
                         GEMM_SMEM);
    cudaFuncSetAttribute(attn_mma, cudaFuncAttributeMaxDynamicSharedMemorySize,
                         ATTN_SMEM);

    ln_kernel<<<TOK, 256>>>(x, ln1_g, ln1_b, ph);
    gemm_mma<<<dim3(H3 / 128, TOK / 128), 256, GEMM_SMEM>>>(
        ph, qkv_w, nullptr, nullptr, pqkv, TOK, H3, E, 0);
    attn_mma<<<dim3(SEQ / 128, NHEAD, 4), 256, ATTN_SMEM>>>(pqkv, pattn);
    gemm_mma<<<dim3(E / 128, TOK / 128), 256, GEMM_SMEM>>>(
        pattn, fc_w, fc_b, x, px1, TOK, E, E, 0);
    ln_kernel<<<TOK, 256>>>(px1, ln2_g, ln2_b, ph);
    gemm_mma<<<dim3(MLPD / 128, TOK / 128), 256, GEMM_SMEM>>>(
        ph, w1, b1, nullptr, pmlp, TOK, MLPD, E, 1);
    gemm_mma<<<dim3(E / 128, TOK / 128), 256, GEMM_SMEM>>>(
        pmlp, w2, b2, px1, out, TOK, E, MLPD, 0);
}

// round 10
// speedup vs baseline: 2.5537x; 1.5762x over previous
#include <cuda_runtime.h>
#include <cuda_fp16.h>
#include <cstdint>
#include <math.h>

#define TOK   8192
#define E     1024
#define H3    3072
#define MLPD  4096
#define NHEAD 16
#define HDIM  64
#define SEQ   2048

// ---------------------------------------------------------------------------
// Scratch: GEMM-consumed activations in fp16; residual streams fp32
// ---------------------------------------------------------------------------
__device__ uint16_t g_h   [(size_t)TOK * E];     // LN out (fp16)
__device__ uint16_t g_qkv [(size_t)TOK * H3];    // qkv, q pre-scaled (fp16)
__device__ uint16_t g_attn[(size_t)TOK * E];     // attention out (fp16)
__device__ float    g_x1  [(size_t)TOK * E];     // residual after attn (fp32)
__device__ uint16_t g_mlp [(size_t)TOK * MLPD];  // gelu(mlp1) (fp16)
__device__ uint16_t g_wq  [(size_t)H3 * E];
__device__ uint16_t g_wf  [(size_t)E * E];
__device__ uint16_t g_w1  [(size_t)MLPD * E];
__device__ uint16_t g_w2  [(size_t)E * MLPD];

#define QSCALE 0.18033688011112042f   // 0.125 * log2(e)

__device__ __forceinline__ uint32_t smem_u32(const void* p) {
    uint32_t a;
    asm("{ .reg .u64 t; cvta.to.shared.u64 t, %1; cvt.u32.u64 %0, t; }"
        : "=r"(a) : "l"(p));
    return a;
}

#define LDSM_X4(r, addr) \
    asm volatile("ldmatrix.sync.aligned.m8n8.x4.shared.b16 {%0,%1,%2,%3}, [%4];" \
        : "=r"((r)[0]), "=r"((r)[1]), "=r"((r)[2]), "=r"((r)[3]) : "r"(addr))

#define LDSM_X4_T(r, addr) \
    asm volatile("ldmatrix.sync.aligned.m8n8.x4.trans.shared.b16 {%0,%1,%2,%3}, [%4];" \
        : "=r"((r)[0]), "=r"((r)[1]), "=r"((r)[2]), "=r"((r)[3]) : "r"(addr))

__device__ __forceinline__ void mma_f16(float* c, const uint32_t* a, const uint32_t* b) {
    asm volatile(
        "mma.sync.aligned.m16n8k16.row.col.f32.f16.f16.f32 "
        "{%0,%1,%2,%3}, {%4,%5,%6,%7}, {%8,%9}, {%0,%1,%2,%3};"
        : "+f"(c[0]), "+f"(c[1]), "+f"(c[2]), "+f"(c[3])
        : "r"(a[0]), "r"(a[1]), "r"(a[2]), "r"(a[3]), "r"(b[0]), "r"(b[1]));
}

__device__ __forceinline__ uint32_t pack_f16(float c0, float c1) {
    uint32_t h;
    asm("cvt.rn.f16x2.f32 %0, %1, %2;" : "=r"(h) : "f"(c1), "f"(c0));
    return h;
}

__device__ __forceinline__ void split_pack(float c0, float c1,
                                           uint32_t& hi, uint32_t& lo)
{
    asm("cvt.rn.f16x2.f32 %0, %1, %2;" : "=r"(hi) : "f"(c1), "f"(c0));
    __half2 h2 = *reinterpret_cast<__half2*>(&hi);
    float l0 = c0 - __low2float(h2);
    float l1 = c1 - __high2float(h2);
    asm("cvt.rn.f16x2.f32 %0, %1, %2;" : "=r"(lo) : "f"(l1), "f"(l0));
}

__device__ __forceinline__ float ex2(float x) {
    float r;
    asm("ex2.approx.f32 %0, %1;" : "=f"(r) : "f"(x));
    return r;
}

__device__ __forceinline__ void cpa16(uint32_t dst, const void* src) {
    asm volatile("cp.async.cg.shared.global [%0], [%1], 16;"
                 :: "r"(dst), "l"(src));
}
#define CP_COMMIT() asm volatile("cp.async.commit_group;" ::: "memory")
#define CP_WAIT0()  asm volatile("cp.async.wait_group 0;" ::: "memory")

// ---------------------------------------------------------------------------
// Weight pre-convert fp32 -> fp16
// ---------------------------------------------------------------------------
__global__ void wconv(const float* __restrict__ src, uint16_t* __restrict__ dst,
                      int n4)
{
    int i = blockIdx.x * 256 + threadIdx.x;
    if (i < n4) {
        float4 v = ((const float4*)src)[i];
        ((uint2*)dst)[i] = make_uint2(pack_f16(v.x, v.y), pack_f16(v.z, v.w));
    }
}

// ---------------------------------------------------------------------------
// LayerNorm: fp32 in -> fp16 out
// ---------------------------------------------------------------------------
__global__ void ln_kernel(const float* __restrict__ x,
                          const float* __restrict__ g,
                          const float* __restrict__ b,
                          uint16_t* __restrict__ y)
{
    int row = blockIdx.x;
    int tid = threadIdx.x;
    const float4* xr = (const float4*)(x + (size_t)row * E);
    float4 v = xr[tid];

    float s  = v.x + v.y + v.z + v.w;
    float ss = v.x * v.x + v.y * v.y + v.z * v.z + v.w * v.w;

    __shared__ float sbuf[32], sbuf2[32];
    #pragma unroll
    for (int o = 16; o > 0; o >>= 1) {
        s  += __shfl_down_sync(0xffffffffu, s,  o);
        ss += __shfl_down_sync(0xffffffffu, ss, o);
    }
    int warp = tid >> 5, lane = tid & 31;
    if (lane == 0) { sbuf[warp] = s; sbuf2[warp] = ss; }
    __syncthreads();
    if (warp == 0) {
        s  = lane < 8 ? sbuf[lane]  : 0.f;
        ss = lane < 8 ? sbuf2[lane] : 0.f;
        #pragma unroll
        for (int o = 4; o > 0; o >>= 1) {
            s  += __shfl_down_sync(0xffffffffu, s,  o);
            ss += __shfl_down_sync(0xffffffffu, ss, o);
        }
        if (lane == 0) { sbuf[0] = s; sbuf2[0] = ss; }
    }
    __syncthreads();
    float mean = sbuf[0] * (1.0f / E);
    float var  = sbuf2[0] * (1.0f / E) - mean * mean;
    float rstd = rsqrtf(var + 1e-5f);

    float4 gv = ((const float4*)g)[tid];
    float4 bv = ((const float4*)b)[tid];
    float o0 = (v.x - mean) * rstd * gv.x + bv.x;
    float o1 = (v.y - mean) * rstd * gv.y + bv.y;
    float o2 = (v.z - mean) * rstd * gv.z + bv.z;
    float o3 = (v.w - mean) * rstd * gv.w + bv.w;
    *(uint2*)(y + (size_t)row * E + tid * 4) =
        make_uint2(pack_f16(o0, o1), pack_f16(o2, o3));
}

// ---------------------------------------------------------------------------
// fp16 mma.sync NT GEMM with cp.async: C = act(A @ B^T + bias) + res
// A, B fp16. CTA 128x128, BK=32, 8 warps (64x32 each), 2 CTAs/SM.
// smem stage (20480 B): A(10240) B(10240), row stride 80 B (32 fp16 + pad).
// Output: fp32 (outf) and/or fp16 (oh); qcols: cols < qcols scaled by QSCALE.
// ---------------------------------------------------------------------------
#define SROW   80
#define MATB   10240
#define STAGEB 20480
#define GEMM_SMEM (2 * STAGEB)

__device__ __forceinline__ void gemm_issue(uint32_t stg,
    const uint16_t* __restrict__ Ah, const uint16_t* __restrict__ Bh,
    int K, int k0, int tid)
{
    #pragma unroll
    for (int i = 0; i < 2; i++) {
        int c = tid * 2 + i;                 // 0..511
        int r = c >> 2, kc = c & 3;
        uint32_t doff = (uint32_t)(r * SROW + kc * 16);
        size_t soff = (size_t)r * K + k0 + kc * 8;
        cpa16(stg + doff,        Ah + soff);
        cpa16(stg + MATB + doff, Bh + soff);
    }
    CP_COMMIT();
}

__global__ __launch_bounds__(256, 2)
void gemm_mma(const uint16_t* __restrict__ A, const uint16_t* __restrict__ B,
              const float* __restrict__ bias, const float* __restrict__ res,
              float* __restrict__ outf, uint16_t* __restrict__ oh,
              int M, int N, int K, int act, int qcols)
{
    extern __shared__ char sm[];
    uint32_t sb = smem_u32(sm);
    int tid = threadIdx.x, w = tid >> 5, lane = tid & 31;
    int wm = w >> 2, wn = w & 3;
    int bn = blockIdx.x, bm = blockIdx.y;

    const uint16_t* Ab = A + (size_t)bm * 128 * K;
    const uint16_t* Bb = B + (size_t)bn * 128 * K;
    int nch = K >> 5;

    float acc[4][4][4];
    #pragma unroll
    for (int i = 0; i < 4; i++)
        #pragma unroll
        for (int j = 0; j < 4; j++)
            #pragma unroll
            for (int c = 0; c < 4; c++) acc[i][j][c] = 0.f;

    gemm_issue(sb, Ab, Bb, K, 0, tid);
    CP_WAIT0();
    __syncthreads();

    uint32_t a_row = (uint32_t)(wm * 64 + (lane & 15)) * SROW + ((lane >> 4) * 8) * 2;
    uint32_t b_row = (uint32_t)(wn * 32 + (lane & 7) + ((lane >> 4) & 1) * 8) * SROW
                   + (((lane >> 3) & 1) * 8) * 2;

    for (int k = 0; k < nch; k++) {
        if (k + 1 < nch)
            gemm_issue(sb + (uint32_t)((k + 1) & 1) * STAGEB, Ab, Bb,
                       K, (k + 1) * 32, tid);

        uint32_t stg = sb + (uint32_t)(k & 1) * STAGEB;
        #pragma unroll
        for (int ks = 0; ks < 2; ks++) {
            uint32_t koff = (uint32_t)(ks * 32);
            uint32_t ah[4][4], bh[2][4];
            #pragma unroll
            for (int mf = 0; mf < 4; mf++)
                LDSM_X4(ah[mf], stg + a_row + (uint32_t)(mf * 16) * SROW + koff);
            #pragma unroll
            for (int np = 0; np < 2; np++)
                LDSM_X4(bh[np], stg + MATB + b_row + (uint32_t)(np * 16) * SROW + koff);
            #pragma unroll
            for (int mf = 0; mf < 4; mf++)
                #pragma unroll
                for (int nf = 0; nf < 4; nf++)
                    mma_f16(acc[mf][nf], ah[mf], &bh[nf >> 1][(nf & 1) * 2]);
        }
        CP_WAIT0();
        __syncthreads();
    }

    int g = lane >> 2, tig = lane & 3;
    #pragma unroll
    for (int mf = 0; mf < 4; mf++) {
        #pragma unroll
        for (int h2 = 0; h2 < 2; h2++) {
            int row = bm * 128 + wm * 64 + mf * 16 + g + h2 * 8;
            size_t rb = (size_t)row * N;
            #pragma unroll
            for (int nf = 0; nf < 4; nf++) {
                int col = bn * 128 + wn * 32 + nf * 8 + tig * 2;
                float v0 = acc[mf][nf][h2 * 2 + 0];
                float v1 = acc[mf][nf][h2 * 2 + 1];
                if (bias) {
                    float2 bv = *(const float2*)(bias + col);
                    v0 += bv.x; v1 += bv.y;
                }
                if (act == 1) {
                    v0 = 0.5f * v0 * (1.0f + erff(v0 * 0.70710678118654752f));
                    v1 = 0.5f * v1 * (1.0f + erff(v1 * 0.70710678118654752f));
                }
                if (res) {
                    float2 rv = *(const float2*)(res + rb + col);
                    v0 += rv.x; v1 += rv.y;
                }
                if (outf)
                    *(float2*)(outf + rb + col) = make_float2(v0, v1);
                if (oh) {
                    float s0 = v0, s1 = v1;
                    if (col < qcols) { s0 *= QSCALE; s1 *= QSCALE; }
                    *(uint32_t*)(oh + rb + col) = pack_f16(s0, s1);
                }
            }
        }
    }
}

// ---------------------------------------------------------------------------
// fp16 flash attention: qkv fp16 (q pre-scaled), pure cp.async loads.
// CTA: 128 Q rows x (head,batch). 256 threads. KV tiles 64, double-buffered.
// smem: Q(18432), 2 stages of [K(9216) V(9216)].
// ---------------------------------------------------------------------------
#define AROW 144
#define KV0  18432
#define KVSTG 18432
#define ATTN_SMEM (KV0 + 2 * KVSTG)

__device__ __forceinline__ void attn_issue(uint32_t stg,
    const uint16_t* __restrict__ qkv, int b, int h, int kt, int tid)
{
    #pragma unroll
    for (int i = 0; i < 2; i++) {
        int c = i * 256 + tid;                // 0..511
        int rr = c >> 3, kc = c & 7;
        size_t base = (size_t)(b * SEQ + kt * 64 + rr) * H3 + h * HDIM + kc * 8;
        uint32_t doff = (uint32_t)(rr * AROW + kc * 16);
        cpa16(stg + doff,        qkv + base + E);       // K
        cpa16(stg + 9216 + doff, qkv + base + 2 * E);   // V
    }
    CP_COMMIT();
}

__global__ __launch_bounds__(256, 2)
void attn_mma(const uint16_t* __restrict__ qkv, uint16_t* __restrict__ out)
{
    extern __shared__ char sm[];
    uint32_t sb = smem_u32(sm);
    int qt = blockIdx.x, h = blockIdx.y, b = blockIdx.z;
    int tid = threadIdx.x, w = tid >> 5, lane = tid & 31;
    int g = lane >> 2, tig = lane & 3;

    // Q tile: 128 rows x 64 fp16 = 1024 16B-chunks, cp.async
    #pragma unroll
    for (int i = 0; i < 4; i++) {
        int idx = i * 256 + tid;
        int r = idx >> 3, kc = idx & 7;
        size_t t = (size_t)(b * SEQ + qt * 128 + r) * H3 + h * HDIM + kc * 8;
        cpa16(sb + (uint32_t)(r * AROW + kc * 16), qkv + t);
    }
    CP_COMMIT();
    attn_issue(sb + KV0, qkv, b, h, 0, tid);
    CP_WAIT0();
    __syncthreads();

    // preload Q fragments (this warp's 16 rows, 4 k-steps)
    uint32_t qh[4][4];
    {
        uint32_t qa = sb + (uint32_t)(w * 16 + (lane & 15)) * AROW
                    + ((lane >> 4) * 8) * 2;
        #pragma unroll
        for (int ks = 0; ks < 4; ks++)
            LDSM_X4(qh[ks], qa + (uint32_t)(ks * 32));
    }

    float o[8][4];
    #pragma unroll
    for (int nf = 0; nf < 8; nf++)
        #pragma unroll
        for (int c = 0; c < 4; c++) o[nf][c] = 0.f;
    float m_[2] = {-1e30f, -1e30f};
    float l_[2] = {0.f, 0.f};

    uint32_t kb_off = (uint32_t)((lane & 7) + ((lane >> 4) & 1) * 8) * AROW
                    + (((lane >> 3) & 1) * 8) * 2;
    uint32_t vb_off = (uint32_t)(lane & 15) * AROW + ((lane >> 4) * 8) * 2 + 9216;

    for (int kt = 0; kt < SEQ / 64; kt++) {
        uint32_t stg = sb + KV0 + (uint32_t)(kt & 1) * KVSTG;

        if (kt + 1 < SEQ / 64)
            attn_issue(sb + KV0 + (uint32_t)((kt + 1) & 1) * KVSTG,
                       qkv, b, h, kt + 1, tid);

        // ---- S = Q K^T (1 MMA) ----
        float s[8][4];
        #pragma unroll
        for (int nf = 0; nf < 8; nf++)
            #pragma unroll
            for (int c = 0; c < 4; c++) s[nf][c] = 0.f;

        #pragma unroll
        for (int ks = 0; ks < 4; ks++) {
            uint32_t koff = (uint32_t)(ks * 32);
            #pragma unroll
            for (int ng = 0; ng < 4; ng++) {
                uint32_t kh[4];
                LDSM_X4(kh, stg + kb_off + (uint32_t)(ng * 16) * AROW + koff);
                #pragma unroll
                for (int j = 0; j < 2; j++)
                    mma_f16(s[ng * 2 + j], qh[ks], &kh[j * 2]);
            }
        }

        // ---- online softmax (base 2) ----
        #pragma unroll
        for (int hh = 0; hh < 2; hh++) {
            float mx = s[0][hh * 2];
            #pragma unroll
            for (int nf = 0; nf < 8; nf++) {
                mx = fmaxf(mx, s[nf][hh * 2 + 0]);
                mx = fmaxf(mx, s[nf][hh * 2 + 1]);
            }
            mx = fmaxf(mx, __shfl_xor_sync(0xffffffffu, mx, 1));
            mx = fmaxf(mx, __shfl_xor_sync(0xffffffffu, mx, 2));
            float mn = fmaxf(m_[hh], mx);
            float alpha = ex2(m_[hh] - mn);
            m_[hh] = mn;
            float lsum = 0.f;
            #pragma unroll
            for (int nf = 0; nf < 8; nf++) {
                float p0 = ex2(s[nf][hh * 2 + 0] - mn);
                float p1 = ex2(s[nf][hh * 2 + 1] - mn);
                s[nf][hh * 2 + 0] = p0;
                s[nf][hh * 2 + 1] = p1;
                lsum += p0 + p1;
                o[nf][hh * 2 + 0] *= alpha;
                o[nf][hh * 2 + 1] *= alpha;
            }
            l_[hh] = l_[hh] * alpha + lsum;
        }

        // ---- O += P V (P split pair, V fp16) ----
        #pragma unroll
        for (int ks = 0; ks < 4; ks++) {
            uint32_t ph[4], pl[4];
            split_pack(s[ks*2  ][0], s[ks*2  ][1], ph[0], pl[0]);
            split_pack(s[ks*2  ][2], s[ks*2  ][3], ph[1], pl[1]);
            split_pack(s[ks*2+1][0], s[ks*2+1][1], ph[2], pl[2]);
            split_pack(s[ks*2+1][2], s[ks*2+1][3], ph[3], pl[3]);
            #pragma unroll
            for (int nd = 0; nd < 4; nd++) {
                uint32_t vh[4];
                LDSM_X4_T(vh, stg + vb_off + (uint32_t)(ks * 16) * AROW
                              + (uint32_t)(nd * 16) * 2);
                #pragma unroll
                for (int j = 0; j < 2; j++) {
                    int nf = nd * 2 + j;
                    mma_f16(o[nf], ph, &vh[j * 2]);
                    mma_f16(o[nf], pl, &vh[j * 2]);
                }
            }
        }

        CP_WAIT0();
        __syncthreads();
    }

    // ---- finalize: write fp16 ----
    #pragma unroll
    for (int hh = 0; hh < 2; hh++) {
        float lt = l_[hh];
        lt += __shfl_xor_sync(0xffffffffu, lt, 1);
        lt += __shfl_xor_sync(0xffffffffu, lt, 2);
        float inv = 1.0f / lt;
        int row = qt * 128 + w * 16 + g + hh * 8;
        size_t base = (size_t)(b * SEQ + row) * E + h * HDIM;
        #pragma unroll
        for (int nf = 0; nf < 8; nf++) {
            int col = nf * 8 + tig * 2;
            *(uint32_t*)(out + base + col) =
                pack_f16(o[nf][hh * 2 + 0] * inv, o[nf][hh * 2 + 1] * inv);
        }
    }
}

// ---------------------------------------------------------------------------
// Launch
// ---------------------------------------------------------------------------
extern "C" void kernel_launch(void* const* d_in, const int* in_sizes, int n_in,
                              void* d_out, int out_size)
{
    const float* x     = (const float*)d_in[0];
    const float* qkv_w = (const float*)d_in[1];
    const float* fc_w  = (const float*)d_in[2];
    const float* fc_b  = (const float*)d_in[3];
    const float* ln1_g = (const float*)d_in[4];
    const float* ln1_b = (const float*)d_in[5];
    const float* ln2_g = (const float*)d_in[6];
    const float* ln2_b = (const float*)d_in[7];
    const float* w1    = (const float*)d_in[8];
    const float* b1    = (const float*)d_in[9];
    const float* w2    = (const float*)d_in[10];
    const float* b2    = (const float*)d_in[11];
    float* out = (float*)d_out;

    uint16_t *ph, *pqkv, *pattn, *pmlp, *wq, *wf, *ww1, *ww2;
    float* px1;
    cudaGetSymbolAddress((void**)&ph,    g_h);
    cudaGetSymbolAddress((void**)&pqkv,  g_qkv);
    cudaGetSymbolAddress((void**)&pattn, g_attn);
    cudaGetSymbolAddress((void**)&pmlp,  g_mlp);
    cudaGetSymbolAddress((void**)&px1,   g_x1);
    cudaGetSymbolAddress((void**)&wq,    g_wq);
    cudaGetSymbolAddress((void**)&wf,    g_wf);
    cudaGetSymbolAddress((void**)&ww1,   g_w1);
    cudaGetSymbolAddress((void**)&ww2,   g_w2);

    cudaFuncSetAttribute(gemm_mma, cudaFuncAttributeMaxDynamicSharedMemorySize,
                         GEMM_SMEM);
    cudaFuncSetAttribute(attn_mma, cudaFuncAttributeMaxDynamicSharedMemorySize,
                         ATTN_SMEM);

    // weight pre-convert
    wconv<<<(H3 * E / 4 + 255) / 256, 256>>>(qkv_w, wq, H3 * E / 4);
    wconv<<<(E * E / 4 + 255) / 256, 256>>>(fc_w, wf, E * E / 4);
    wconv<<<(MLPD * E / 4 + 255) / 256, 256>>>(w1, ww1, MLPD * E / 4);
    wconv<<<(E * MLPD / 4 + 255) / 256, 256>>>(w2, ww2, E * MLPD / 4);

    // 1. h = LN1(x) -> fp16
    ln_kernel<<<TOK, 256>>>(x, ln1_g, ln1_b, ph);
    // 2. qkv = h @ qkv_w^T -> fp16 (q cols pre-scaled)
    gemm_mma<<<dim3(H3 / 128, TOK / 128), 256, GEMM_SMEM>>>(
        ph, wq, nullptr, nullptr, nullptr, pqkv, TOK, H3, E, 0, E);
    // 3. attention -> fp16
    attn_mma<<<dim3(SEQ / 128, NHEAD, 4), 256, ATTN_SMEM>>>(pqkv, pattn);
    // 4. x1 = x + attn @ fc_w^T + fc_b -> fp32
    gemm_mma<<<dim3(E / 128, TOK / 128), 256, GEMM_SMEM>>>(
        pattn, wf, fc_b, x, px1, nullptr, TOK, E, E, 0, 0);
    // 5. h = LN2(x1) -> fp16
    ln_kernel<<<TOK, 256>>>(px1, ln2_g, ln2_b, ph);
    // 6. mlp = gelu(h @ w1^T + b1) -> fp16
    gemm_mma<<<dim3(MLPD / 128, TOK / 128), 256, GEMM_SMEM>>>(
        ph, ww1, b1, nullptr, nullptr, pmlp, TOK, MLPD, E, 1, 0);
    // 7. out = x1 + mlp @ w2^T + b2 -> fp32
    gemm_mma<<<dim3(E / 128, TOK / 128), 256, GEMM_SMEM>>>(
        pmlp, ww2, b2, px1, out, nullptr, TOK, E, MLPD, 0, 0);
}

// round 11
// speedup vs baseline: 2.7410x; 1.0734x over previous
#include <cuda_runtime.h>
#include <cuda_fp16.h>
#include <cstdint>
#include <math.h>

#define TOK   8192
#define E     1024
#define H3    3072
#define MLPD  4096
#define NHEAD 16
#define HDIM  64
#define SEQ   2048

// ---------------------------------------------------------------------------
// Scratch: GEMM-consumed activations in fp16; residual streams fp32
// ---------------------------------------------------------------------------
__device__ uint16_t g_h   [(size_t)TOK * E];
__device__ uint16_t g_qkv [(size_t)TOK * H3];
__device__ uint16_t g_attn[(size_t)TOK * E];
__device__ float    g_x1  [(size_t)TOK * E];
__device__ uint16_t g_mlp [(size_t)TOK * MLPD];
__device__ uint16_t g_wq  [(size_t)H3 * E];
__device__ uint16_t g_wf  [(size_t)E * E];
__device__ uint16_t g_w1  [(size_t)MLPD * E];
__device__ uint16_t g_w2  [(size_t)E * MLPD];

#define QSCALE 0.18033688011112042f   // 0.125 * log2(e)

__device__ __forceinline__ uint32_t smem_u32(const void* p) {
    uint32_t a;
    asm("{ .reg .u64 t; cvta.to.shared.u64 t, %1; cvt.u32.u64 %0, t; }"
        : "=r"(a) : "l"(p));
    return a;
}

#define LDSM_X4(r, addr) \
    asm volatile("ldmatrix.sync.aligned.m8n8.x4.shared.b16 {%0,%1,%2,%3}, [%4];" \
        : "=r"((r)[0]), "=r"((r)[1]), "=r"((r)[2]), "=r"((r)[3]) : "r"(addr))

#define LDSM_X4_T(r, addr) \
    asm volatile("ldmatrix.sync.aligned.m8n8.x4.trans.shared.b16 {%0,%1,%2,%3}, [%4];" \
        : "=r"((r)[0]), "=r"((r)[1]), "=r"((r)[2]), "=r"((r)[3]) : "r"(addr))

__device__ __forceinline__ void mma_f16(float* c, const uint32_t* a, const uint32_t* b) {
    asm volatile(
        "mma.sync.aligned.m16n8k16.row.col.f32.f16.f16.f32 "
        "{%0,%1,%2,%3}, {%4,%5,%6,%7}, {%8,%9}, {%0,%1,%2,%3};"
        : "+f"(c[0]), "+f"(c[1]), "+f"(c[2]), "+f"(c[3])
        : "r"(a[0]), "r"(a[1]), "r"(a[2]), "r"(a[3]), "r"(b[0]), "r"(b[1]));
}

__device__ __forceinline__ uint32_t pack_f16(float c0, float c1) {
    uint32_t h;
    asm("cvt.rn.f16x2.f32 %0, %1, %2;" : "=r"(h) : "f"(c1), "f"(c0));
    return h;
}

__device__ __forceinline__ float ex2(float x) {
    float r;
    asm("ex2.approx.f32 %0, %1;" : "=f"(r) : "f"(x));
    return r;
}

__device__ __forceinline__ void cpa16(uint32_t dst, const void* src) {
    asm volatile("cp.async.cg.shared.global [%0], [%1], 16;"
                 :: "r"(dst), "l"(src));
}
#define CP_COMMIT() asm volatile("cp.async.commit_group;" ::: "memory")
#define CP_WAIT0()  asm volatile("cp.async.wait_group 0;" ::: "memory")
#define CP_WAIT1()  asm volatile("cp.async.wait_group 1;" ::: "memory")

// ---------------------------------------------------------------------------
// Weight pre-convert fp32 -> fp16
// ---------------------------------------------------------------------------
__global__ void wconv(const float* __restrict__ src, uint16_t* __restrict__ dst,
                      int n4)
{
    int i = blockIdx.x * 256 + threadIdx.x;
    if (i < n4) {
        float4 v = ((const float4*)src)[i];
        ((uint2*)dst)[i] = make_uint2(pack_f16(v.x, v.y), pack_f16(v.z, v.w));
    }
}

// ---------------------------------------------------------------------------
// LayerNorm: fp32 in -> fp16 out
// ---------------------------------------------------------------------------
__global__ void ln_kernel(const float* __restrict__ x,
                          const float* __restrict__ g,
                          const float* __restrict__ b,
                          uint16_t* __restrict__ y)
{
    int row = blockIdx.x;
    int tid = threadIdx.x;
    const float4* xr = (const float4*)(x + (size_t)row * E);
    float4 v = xr[tid];

    float s  = v.x + v.y + v.z + v.w;
    float ss = v.x * v.x + v.y * v.y + v.z * v.z + v.w * v.w;

    __shared__ float sbuf[32], sbuf2[32];
    #pragma unroll
    for (int o = 16; o > 0; o >>= 1) {
        s  += __shfl_down_sync(0xffffffffu, s,  o);
        ss += __shfl_down_sync(0xffffffffu, ss, o);
    }
    int warp = tid >> 5, lane = tid & 31;
    if (lane == 0) { sbuf[warp] = s; sbuf2[warp] = ss; }
    __syncthreads();
    if (warp == 0) {
        s  = lane < 8 ? sbuf[lane]  : 0.f;
        ss = lane < 8 ? sbuf2[lane] : 0.f;
        #pragma unroll
        for (int o = 4; o > 0; o >>= 1) {
            s  += __shfl_down_sync(0xffffffffu, s,  o);
            ss += __shfl_down_sync(0xffffffffu, ss, o);
        }
        if (lane == 0) { sbuf[0] = s; sbuf2[0] = ss; }
    }
    __syncthreads();
    float mean = sbuf[0] * (1.0f / E);
    float var  = sbuf2[0] * (1.0f / E) - mean * mean;
    float rstd = rsqrtf(var + 1e-5f);

    float4 gv = ((const float4*)g)[tid];
    float4 bv = ((const float4*)b)[tid];
    float o0 = (v.x - mean) * rstd * gv.x + bv.x;
    float o1 = (v.y - mean) * rstd * gv.y + bv.y;
    float o2 = (v.z - mean) * rstd * gv.z + bv.z;
    float o3 = (v.w - mean) * rstd * gv.w + bv.w;
    *(uint2*)(y + (size_t)row * E + tid * 4) =
        make_uint2(pack_f16(o0, o1), pack_f16(o2, o3));
}

// ---------------------------------------------------------------------------
// fp16 mma.sync NT GEMM, 3-stage cp.async ring.
// CTA 128x128, BK=32, 8 warps (64x32 each), 2 CTAs/SM.
// ---------------------------------------------------------------------------
#define SROW   80
#define MATB   10240
#define STAGEB 20480
#define GEMM_SMEM (3 * STAGEB)

__device__ __forceinline__ void gemm_issue(uint32_t stg,
    const uint16_t* __restrict__ Ah, const uint16_t* __restrict__ Bh,
    int K, int k0, int tid)
{
    #pragma unroll
    for (int i = 0; i < 2; i++) {
        int c = tid * 2 + i;                 // 0..511
        int r = c >> 2, kc = c & 3;
        uint32_t doff = (uint32_t)(r * SROW + kc * 16);
        size_t soff = (size_t)r * K + k0 + kc * 8;
        cpa16(stg + doff,        Ah + soff);
        cpa16(stg + MATB + doff, Bh + soff);
    }
    CP_COMMIT();
}

__global__ __launch_bounds__(256, 2)
void gemm_mma(const uint16_t* __restrict__ A, const uint16_t* __restrict__ B,
              const float* __restrict__ bias, const float* __restrict__ res,
              float* __restrict__ outf, uint16_t* __restrict__ oh,
              int M, int N, int K, int act, int qcols)
{
    extern __shared__ char sm[];
    uint32_t sb = smem_u32(sm);
    int tid = threadIdx.x, w = tid >> 5, lane = tid & 31;
    int wm = w >> 2, wn = w & 3;
    int bn = blockIdx.x, bm = blockIdx.y;

    const uint16_t* Ab = A + (size_t)bm * 128 * K;
    const uint16_t* Bb = B + (size_t)bn * 128 * K;
    int nch = K >> 5;

    float acc[4][4][4];
    #pragma unroll
    for (int i = 0; i < 4; i++)
        #pragma unroll
        for (int j = 0; j < 4; j++)
            #pragma unroll
            for (int c = 0; c < 4; c++) acc[i][j][c] = 0.f;

    gemm_issue(sb, Ab, Bb, K, 0, tid);
    if (nch > 1) gemm_issue(sb + STAGEB, Ab, Bb, K, 32, tid);

    uint32_t a_row = (uint32_t)(wm * 64 + (lane & 15)) * SROW + ((lane >> 4) * 8) * 2;
    uint32_t b_row = (uint32_t)(wn * 32 + (lane & 7) + ((lane >> 4) & 1) * 8) * SROW
                   + (((lane >> 3) & 1) * 8) * 2;

    int buf = 0;
    for (int k = 0; k < nch; k++) {
        if (k + 1 < nch) CP_WAIT1(); else CP_WAIT0();
        __syncthreads();
        if (k + 2 < nch) {
            int nb = buf + 2; if (nb >= 3) nb -= 3;
            gemm_issue(sb + (uint32_t)nb * STAGEB, Ab, Bb, K, (k + 2) * 32, tid);
        }

        uint32_t stg = sb + (uint32_t)buf * STAGEB;
        #pragma unroll
        for (int ks = 0; ks < 2; ks++) {
            uint32_t koff = (uint32_t)(ks * 32);
            uint32_t ah[4][4], bh[2][4];
            #pragma unroll
            for (int mf = 0; mf < 4; mf++)
                LDSM_X4(ah[mf], stg + a_row + (uint32_t)(mf * 16) * SROW + koff);
            #pragma unroll
            for (int np = 0; np < 2; np++)
                LDSM_X4(bh[np], stg + MATB + b_row + (uint32_t)(np * 16) * SROW + koff);
            #pragma unroll
            for (int mf = 0; mf < 4; mf++)
                #pragma unroll
                for (int nf = 0; nf < 4; nf++)
                    mma_f16(acc[mf][nf], ah[mf], &bh[nf >> 1][(nf & 1) * 2]);
        }
        if (++buf == 3) buf = 0;
    }

    int g = lane >> 2, tig = lane & 3;
    #pragma unroll
    for (int mf = 0; mf < 4; mf++) {
        #pragma unroll
        for (int h2 = 0; h2 < 2; h2++) {
            int row = bm * 128 + wm * 64 + mf * 16 + g + h2 * 8;
            size_t rb = (size_t)row * N;
            #pragma unroll
            for (int nf = 0; nf < 4; nf++) {
                int col = bn * 128 + wn * 32 + nf * 8 + tig * 2;
                float v0 = acc[mf][nf][h2 * 2 + 0];
                float v1 = acc[mf][nf][h2 * 2 + 1];
                if (bias) {
                    float2 bv = *(const float2*)(bias + col);
                    v0 += bv.x; v1 += bv.y;
                }
                if (act == 1) {
                    v0 = 0.5f * v0 * (1.0f + erff(v0 * 0.70710678118654752f));
                    v1 = 0.5f * v1 * (1.0f + erff(v1 * 0.70710678118654752f));
                }
                if (res) {
                    float2 rv = *(const float2*)(res + rb + col);
                    v0 += rv.x; v1 += rv.y;
                }
                if (outf)
                    *(float2*)(outf + rb + col) = make_float2(v0, v1);
                if (oh) {
                    float s0 = v0, s1 = v1;
                    if (col < qcols) { s0 *= QSCALE; s1 *= QSCALE; }
                    *(uint32_t*)(oh + rb + col) = pack_f16(s0, s1);
                }
            }
        }
    }
}

// ---------------------------------------------------------------------------
// fp16 flash attention: P quantized to fp16 (1-MMA PV).
// CTA: 128 Q rows x (head,batch). 256 threads. KV tiles 64, double-buffered.
// ---------------------------------------------------------------------------
#define AROW 144
#define KV0  18432
#define KVSTG 18432
#define ATTN_SMEM (KV0 + 2 * KVSTG)

__device__ __forceinline__ void attn_issue(uint32_t stg,
    const uint16_t* __restrict__ qkv, int b, int h, int kt, int tid)
{
    #pragma unroll
    for (int i = 0; i < 2; i++) {
        int c = i * 256 + tid;
        int rr = c >> 3, kc = c & 7;
        size_t base = (size_t)(b * SEQ + kt * 64 + rr) * H3 + h * HDIM + kc * 8;
        uint32_t doff = (uint32_t)(rr * AROW + kc * 16);
        cpa16(stg + doff,        qkv + base + E);
        cpa16(stg + 9216 + doff, qkv + base + 2 * E);
    }
    CP_COMMIT();
}

__global__ __launch_bounds__(256, 2)
void attn_mma(const uint16_t* __restrict__ qkv, uint16_t* __restrict__ out)
{
    extern __shared__ char sm[];
    uint32_t sb = smem_u32(sm);
    int qt = blockIdx.x, h = blockIdx.y, b = blockIdx.z;
    int tid = threadIdx.x, w = tid >> 5, lane = tid & 31;
    int g = lane >> 2, tig = lane & 3;

    #pragma unroll
    for (int i = 0; i < 4; i++) {
        int idx = i * 256 + tid;
        int r = idx >> 3, kc = idx & 7;
        size_t t = (size_t)(b * SEQ + qt * 128 + r) * H3 + h * HDIM + kc * 8;
        cpa16(sb + (uint32_t)(r * AROW + kc * 16), qkv + t);
    }
    CP_COMMIT();
    attn_issue(sb + KV0, qkv, b, h, 0, tid);
    CP_WAIT0();
    __syncthreads();

    uint32_t qh[4][4];
    {
        uint32_t qa = sb + (uint32_t)(w * 16 + (lane & 15)) * AROW
                    + ((lane >> 4) * 8) * 2;
        #pragma unroll
        for (int ks = 0; ks < 4; ks++)
            LDSM_X4(qh[ks], qa + (uint32_t)(ks * 32));
    }

    float o[8][4];
    #pragma unroll
    for (int nf = 0; nf < 8; nf++)
        #pragma unroll
        for (int c = 0; c < 4; c++) o[nf][c] = 0.f;
    float m_[2] = {-1e30f, -1e30f};
    float l_[2] = {0.f, 0.f};

    uint32_t kb_off = (uint32_t)((lane & 7) + ((lane >> 4) & 1) * 8) * AROW
                    + (((lane >> 3) & 1) * 8) * 2;
    uint32_t vb_off = (uint32_t)(lane & 15) * AROW + ((lane >> 4) * 8) * 2 + 9216;

    for (int kt = 0; kt < SEQ / 64; kt++) {
        uint32_t stg = sb + KV0 + (uint32_t)(kt & 1) * KVSTG;

        if (kt + 1 < SEQ / 64)
            attn_issue(sb + KV0 + (uint32_t)((kt + 1) & 1) * KVSTG,
                       qkv, b, h, kt + 1, tid);

        // ---- S = Q K^T ----
        float s[8][4];
        #pragma unroll
        for (int nf = 0; nf < 8; nf++)
            #pragma unroll
            for (int c = 0; c < 4; c++) s[nf][c] = 0.f;

        #pragma unroll
        for (int ks = 0; ks < 4; ks++) {
            uint32_t koff = (uint32_t)(ks * 32);
            #pragma unroll
            for (int ng = 0; ng < 4; ng++) {
                uint32_t kh[4];
                LDSM_X4(kh, stg + kb_off + (uint32_t)(ng * 16) * AROW + koff);
                #pragma unroll
                for (int j = 0; j < 2; j++)
                    mma_f16(s[ng * 2 + j], qh[ks], &kh[j * 2]);
            }
        }

        // ---- online softmax (base 2) ----
        #pragma unroll
        for (int hh = 0; hh < 2; hh++) {
            float mx = s[0][hh * 2];
            #pragma unroll
            for (int nf = 0; nf < 8; nf++) {
                mx = fmaxf(mx, s[nf][hh * 2 + 0]);
                mx = fmaxf(mx, s[nf][hh * 2 + 1]);
            }
            mx = fmaxf(mx, __shfl_xor_sync(0xffffffffu, mx, 1));
            mx = fmaxf(mx, __shfl_xor_sync(0xffffffffu, mx, 2));
            float mn = fmaxf(m_[hh], mx);
            float alpha = ex2(m_[hh] - mn);
            m_[hh] = mn;
            float lsum = 0.f;
            #pragma unroll
            for (int nf = 0; nf < 8; nf++) {
                float p0 = ex2(s[nf][hh * 2 + 0] - mn);
                float p1 = ex2(s[nf][hh * 2 + 1] - mn);
                s[nf][hh * 2 + 0] = p0;
                s[nf][hh * 2 + 1] = p1;
                lsum += p0 + p1;
                o[nf][hh * 2 + 0] *= alpha;
                o[nf][hh * 2 + 1] *= alpha;
            }
            l_[hh] = l_[hh] * alpha + lsum;
        }

        // ---- O += P V (P fp16, 1 MMA) ----
        #pragma unroll
        for (int ks = 0; ks < 4; ks++) {
            uint32_t ph[4];
            ph[0] = pack_f16(s[ks*2  ][0], s[ks*2  ][1]);
            ph[1] = pack_f16(s[ks*2  ][2], s[ks*2  ][3]);
            ph[2] = pack_f16(s[ks*2+1][0], s[ks*2+1][1]);
            ph[3] = pack_f16(s[ks*2+1][2], s[ks*2+1][3]);
            #pragma unroll
            for (int nd = 0; nd < 4; nd++) {
                uint32_t vh[4];
                LDSM_X4_T(vh, stg + vb_off + (uint32_t)(ks * 16) * AROW
                              + (uint32_t)(nd * 16) * 2);
                #pragma unroll
                for (int j = 0; j < 2; j++)
                    mma_f16(o[nd * 2 + j], ph, &vh[j * 2]);
            }
        }

        CP_WAIT0();
        __syncthreads();
    }

    // ---- finalize ----
    #pragma unroll
    for (int hh = 0; hh < 2; hh++) {
        float lt = l_[hh];
        lt += __shfl_xor_sync(0xffffffffu, lt, 1);
        lt += __shfl_xor_sync(0xffffffffu, lt, 2);
        float inv = 1.0f / lt;
        int row = qt * 128 + w * 16 + g + hh * 8;
        size_t base = (size_t)(b * SEQ + row) * E + h * HDIM;
        #pragma unroll
        for (int nf = 0; nf < 8; nf++) {
            int col = nf * 8 + tig * 2;
            *(uint32_t*)(out + base + col) =
                pack_f16(o[nf][hh * 2 + 0] * inv, o[nf][hh * 2 + 1] * inv);
        }
    }
}

// ---------------------------------------------------------------------------
// Launch
// ---------------------------------------------------------------------------
extern "C" void kernel_launch(void* const* d_in, const int* in_sizes, int n_in,
                              void* d_out, int out_size)
{
    const float* x     = (const float*)d_in[0];
    const float* qkv_w = (const float*)d_in[1];
    const float* fc_w  = (const float*)d_in[2];
    const float* fc_b  = (const float*)d_in[3];
    const float* ln1_g = (const float*)d_in[4];
    const float* ln1_b = (const float*)d_in[5];
    const float* ln2_g = (const float*)d_in[6];
    const float* ln2_b = (const float*)d_in[7];
    const float* w1    = (const float*)d_in[8];
    const float* b1    = (const float*)d_in[9];
    const float* w2    = (const float*)d_in[10];
    const float* b2    = (const float*)d_in[11];
    float* out = (float*)d_out;

    uint16_t *ph, *pqkv, *pattn, *pmlp, *wq, *wf, *ww1, *ww2;
    float* px1;
    cudaGetSymbolAddress((void**)&ph,    g_h);
    cudaGetSymbolAddress((void**)&pqkv,  g_qkv);
    cudaGetSymbolAddress((void**)&pattn, g_attn);
    cudaGetSymbolAddress((void**)&pmlp,  g_mlp);
    cudaGetSymbolAddress((void**)&px1,   g_x1);
    cudaGetSymbolAddress((void**)&wq,    g_wq);
    cudaGetSymbolAddress((void**)&wf,    g_wf);
    cudaGetSymbolAddress((void**)&ww1,   g_w1);
    cudaGetSymbolAddress((void**)&ww2,   g_w2);

    cudaFuncSetAttribute(gemm_mma, cudaFuncAttributeMaxDynamicSharedMemorySize,
                         GEMM_SMEM);
    cudaFuncSetAttribute(attn_mma, cudaFuncAttributeMaxDynamicSharedMemorySize,
                         ATTN_SMEM);

    wconv<<<(H3 * E / 4 + 255) / 256, 256>>>(qkv_w, wq, H3 * E / 4);
    wconv<<<(E * E / 4 + 255) / 256, 256>>>(fc_w, wf, E * E / 4);
    wconv<<<(MLPD * E / 4 + 255) / 256, 256>>>(w1, ww1, MLPD * E / 4);
    wconv<<<(E * MLPD / 4 + 255) / 256, 256>>>(w2, ww2, E * MLPD / 4);

    ln_kernel<<<TOK, 256>>>(x, ln1_g, ln1_b, ph);
    gemm_mma<<<dim3(H3 / 128, TOK / 128), 256, GEMM_SMEM>>>(
        ph, wq, nullptr, nullptr, nullptr, pqkv, TOK, H3, E, 0, E);
    attn_mma<<<dim3(SEQ / 128, NHEAD, 4), 256, ATTN_SMEM>>>(pqkv, pattn);
    gemm_mma<<<dim3(E / 128, TOK / 128), 256, GEMM_SMEM>>>(
        pattn, wf, fc_b, x, px1, nullptr, TOK, E, E, 0, 0);
    ln_kernel<<<TOK, 256>>>(px1, ln2_g, ln2_b, ph);
    gemm_mma<<<dim3(MLPD / 128, TOK / 128), 256, GEMM_SMEM>>>(
        ph, ww1, b1, nullptr, nullptr, pmlp, TOK, MLPD, E, 1, 0);
    gemm_mma<<<dim3(E / 128, TOK / 128), 256, GEMM_SMEM>>>(
        pmlp, ww2, b2, px1, out, nullptr, TOK, E, MLPD, 0, 0);
}

// round 12
// speedup vs baseline: 3.2941x; 1.2018x over previous
#include <cuda_runtime.h>
#include <cuda_fp16.h>
#include <cstdint>
#include <math.h>

#define TOK   8192
#define E     1024
#define H3    3072
#define MLPD  4096
#define NHEAD 16
#define HDIM  64
#define SEQ   2048

// ---------------------------------------------------------------------------
// Scratch
// ---------------------------------------------------------------------------
__device__ uint16_t g_h   [(size_t)TOK * E];
__device__ uint16_t g_qkv [(size_t)TOK * H3];
__device__ uint16_t g_attn[(size_t)TOK * E];
__device__ float    g_x1  [(size_t)TOK * E];
__device__ uint16_t g_mlp [(size_t)TOK * MLPD];
__device__ uint16_t g_wq  [(size_t)H3 * E];
__device__ uint16_t g_wf  [(size_t)E * E];
__device__ uint16_t g_w1  [(size_t)MLPD * E];
__device__ uint16_t g_w2  [(size_t)E * MLPD];

#define QSCALE 0.18033688011112042f   // 0.125 * log2(e)

__device__ __forceinline__ uint32_t smem_u32(const void* p) {
    uint32_t a;
    asm("{ .reg .u64 t; cvta.to.shared.u64 t, %1; cvt.u32.u64 %0, t; }"
        : "=r"(a) : "l"(p));
    return a;
}

#define LDSM_X4(r, addr) \
    asm volatile("ldmatrix.sync.aligned.m8n8.x4.shared.b16 {%0,%1,%2,%3}, [%4];" \
        : "=r"((r)[0]), "=r"((r)[1]), "=r"((r)[2]), "=r"((r)[3]) : "r"(addr))

#define LDSM_X4_T(r, addr) \
    asm volatile("ldmatrix.sync.aligned.m8n8.x4.trans.shared.b16 {%0,%1,%2,%3}, [%4];" \
        : "=r"((r)[0]), "=r"((r)[1]), "=r"((r)[2]), "=r"((r)[3]) : "r"(addr))

__device__ __forceinline__ void mma_f16(float* c, const uint32_t* a, const uint32_t* b) {
    asm volatile(
        "mma.sync.aligned.m16n8k16.row.col.f32.f16.f16.f32 "
        "{%0,%1,%2,%3}, {%4,%5,%6,%7}, {%8,%9}, {%0,%1,%2,%3};"
        : "+f"(c[0]), "+f"(c[1]), "+f"(c[2]), "+f"(c[3])
        : "r"(a[0]), "r"(a[1]), "r"(a[2]), "r"(a[3]), "r"(b[0]), "r"(b[1]));
}

__device__ __forceinline__ uint32_t pack_f16(float c0, float c1) {
    uint32_t h;
    asm("cvt.rn.f16x2.f32 %0, %1, %2;" : "=r"(h) : "f"(c1), "f"(c0));
    return h;
}

__device__ __forceinline__ float ex2(float x) {
    float r;
    asm("ex2.approx.f32 %0, %1;" : "=f"(r) : "f"(x));
    return r;
}

__device__ __forceinline__ void cpa16(uint32_t dst, const void* src) {
    asm volatile("cp.async.cg.shared.global [%0], [%1], 16;"
                 :: "r"(dst), "l"(src));
}
#define CP_COMMIT() asm volatile("cp.async.commit_group;" ::: "memory")
#define CP_WAIT0()  asm volatile("cp.async.wait_group 0;" ::: "memory")
#define CP_WAIT1()  asm volatile("cp.async.wait_group 1;" ::: "memory")

// ---------------------------------------------------------------------------
// Weight pre-convert fp32 -> fp16
// ---------------------------------------------------------------------------
__global__ void wconv(const float* __restrict__ src, uint16_t* __restrict__ dst,
                      int n4)
{
    int i = blockIdx.x * 256 + threadIdx.x;
    if (i < n4) {
        float4 v = ((const float4*)src)[i];
        ((uint2*)dst)[i] = make_uint2(pack_f16(v.x, v.y), pack_f16(v.z, v.w));
    }
}

// ---------------------------------------------------------------------------
// LayerNorm: fp32 in -> fp16 out
// ---------------------------------------------------------------------------
__global__ void ln_kernel(const float* __restrict__ x,
                          const float* __restrict__ g,
                          const float* __restrict__ b,
                          uint16_t* __restrict__ y)
{
    int row = blockIdx.x;
    int tid = threadIdx.x;
    const float4* xr = (const float4*)(x + (size_t)row * E);
    float4 v = xr[tid];

    float s  = v.x + v.y + v.z + v.w;
    float ss = v.x * v.x + v.y * v.y + v.z * v.z + v.w * v.w;

    __shared__ float sbuf[32], sbuf2[32];
    #pragma unroll
    for (int o = 16; o > 0; o >>= 1) {
        s  += __shfl_down_sync(0xffffffffu, s,  o);
        ss += __shfl_down_sync(0xffffffffu, ss, o);
    }
    int warp = tid >> 5, lane = tid & 31;
    if (lane == 0) { sbuf[warp] = s; sbuf2[warp] = ss; }
    __syncthreads();
    if (warp == 0) {
        s  = lane < 8 ? sbuf[lane]  : 0.f;
        ss = lane < 8 ? sbuf2[lane] : 0.f;
        #pragma unroll
        for (int o = 4; o > 0; o >>= 1) {
            s  += __shfl_down_sync(0xffffffffu, s,  o);
            ss += __shfl_down_sync(0xffffffffu, ss, o);
        }
        if (lane == 0) { sbuf[0] = s; sbuf2[0] = ss; }
    }
    __syncthreads();
    float mean = sbuf[0] * (1.0f / E);
    float var  = sbuf2[0] * (1.0f / E) - mean * mean;
    float rstd = rsqrtf(var + 1e-5f);

    float4 gv = ((const float4*)g)[tid];
    float4 bv = ((const float4*)b)[tid];
    float o0 = (v.x - mean) * rstd * gv.x + bv.x;
    float o1 = (v.y - mean) * rstd * gv.y + bv.y;
    float o2 = (v.z - mean) * rstd * gv.z + bv.z;
    float o3 = (v.w - mean) * rstd * gv.w + bv.w;
    *(uint2*)(y + (size_t)row * E + tid * 4) =
        make_uint2(pack_f16(o0, o1), pack_f16(o2, o3));
}

// ---------------------------------------------------------------------------
// fp16 mma.sync NT GEMM, 3-stage cp.async ring.
// CTA 128x128, BK=32, 4 warps (64x64 each), 128 threads, 2 CTAs/SM.
// ---------------------------------------------------------------------------
#define SROW   80
#define MATB   10240
#define STAGEB 20480
#define GEMM_SMEM (3 * STAGEB)

__device__ __forceinline__ void gemm_issue(uint32_t stg,
    const uint16_t* __restrict__ Ah, const uint16_t* __restrict__ Bh,
    int K, int k0, int tid)
{
    #pragma unroll
    for (int i = 0; i < 4; i++) {
        int c = i * 128 + tid;               // 0..511
        int r = c >> 2, kc = c & 3;
        uint32_t doff = (uint32_t)(r * SROW + kc * 16);
        size_t soff = (size_t)r * K + k0 + kc * 8;
        cpa16(stg + doff,        Ah + soff);
        cpa16(stg + MATB + doff, Bh + soff);
    }
    CP_COMMIT();
}

__global__ __launch_bounds__(128, 2)
void gemm_mma(const uint16_t* __restrict__ A, const uint16_t* __restrict__ B,
              const float* __restrict__ bias, const float* __restrict__ res,
              float* __restrict__ outf, uint16_t* __restrict__ oh,
              int M, int N, int K, int act, int qcols)
{
    extern __shared__ char sm[];
    uint32_t sb = smem_u32(sm);
    int tid = threadIdx.x, w = tid >> 5, lane = tid & 31;
    int wm = w >> 1, wn = w & 1;             // warp tile: rows wm*64, cols wn*64
    int bn = blockIdx.x, bm = blockIdx.y;

    const uint16_t* Ab = A + (size_t)bm * 128 * K;
    const uint16_t* Bb = B + (size_t)bn * 128 * K;
    int nch = K >> 5;

    float acc[4][8][4];
    #pragma unroll
    for (int i = 0; i < 4; i++)
        #pragma unroll
        for (int j = 0; j < 8; j++)
            #pragma unroll
            for (int c = 0; c < 4; c++) acc[i][j][c] = 0.f;

    gemm_issue(sb, Ab, Bb, K, 0, tid);
    if (nch > 1) gemm_issue(sb + STAGEB, Ab, Bb, K, 32, tid);

    uint32_t a_row = (uint32_t)(wm * 64 + (lane & 15)) * SROW + ((lane >> 4) * 8) * 2;
    uint32_t b_row = (uint32_t)(wn * 64 + (lane & 7) + ((lane >> 4) & 1) * 8) * SROW
                   + (((lane >> 3) & 1) * 8) * 2;

    int buf = 0;
    for (int k = 0; k < nch; k++) {
        if (k + 1 < nch) CP_WAIT1(); else CP_WAIT0();
        __syncthreads();
        if (k + 2 < nch) {
            int nb = buf + 2; if (nb >= 3) nb -= 3;
            gemm_issue(sb + (uint32_t)nb * STAGEB, Ab, Bb, K, (k + 2) * 32, tid);
        }

        uint32_t stg = sb + (uint32_t)buf * STAGEB;
        #pragma unroll
        for (int ks = 0; ks < 2; ks++) {
            uint32_t koff = (uint32_t)(ks * 32);
            uint32_t ah[4][4], bh[4][4];
            #pragma unroll
            for (int mf = 0; mf < 4; mf++)
                LDSM_X4(ah[mf], stg + a_row + (uint32_t)(mf * 16) * SROW + koff);
            #pragma unroll
            for (int np = 0; np < 4; np++)
                LDSM_X4(bh[np], stg + MATB + b_row + (uint32_t)(np * 16) * SROW + koff);
            #pragma unroll
            for (int mf = 0; mf < 4; mf++)
                #pragma unroll
                for (int nf = 0; nf < 8; nf++)
                    mma_f16(acc[mf][nf], ah[mf], &bh[nf >> 1][(nf & 1) * 2]);
        }
        if (++buf == 3) buf = 0;
    }

    int g = lane >> 2, tig = lane & 3;
    #pragma unroll
    for (int mf = 0; mf < 4; mf++) {
        #pragma unroll
        for (int h2 = 0; h2 < 2; h2++) {
            int row = bm * 128 + wm * 64 + mf * 16 + g + h2 * 8;
            size_t rb = (size_t)row * N;
            #pragma unroll
            for (int nf = 0; nf < 8; nf++) {
                int col = bn * 128 + wn * 64 + nf * 8 + tig * 2;
                float v0 = acc[mf][nf][h2 * 2 + 0];
                float v1 = acc[mf][nf][h2 * 2 + 1];
                if (bias) {
                    float2 bv = *(const float2*)(bias + col);
                    v0 += bv.x; v1 += bv.y;
                }
                if (act == 1) {
                    v0 = 0.5f * v0 * (1.0f + erff(v0 * 0.70710678118654752f));
                    v1 = 0.5f * v1 * (1.0f + erff(v1 * 0.70710678118654752f));
                }
                if (res) {
                    float2 rv = *(const float2*)(res + rb + col);
                    v0 += rv.x; v1 += rv.y;
                }
                if (outf)
                    *(float2*)(outf + rb + col) = make_float2(v0, v1);
                if (oh) {
                    float s0 = v0, s1 = v1;
                    if (col < qcols) { s0 *= QSCALE; s1 *= QSCALE; }
                    *(uint32_t*)(oh + rb + col) = pack_f16(s0, s1);
                }
            }
        }
    }
}

// ---------------------------------------------------------------------------
// fp16 flash attention (unchanged from R11)
// ---------------------------------------------------------------------------
#define AROW 144
#define KV0  18432
#define KVSTG 18432
#define ATTN_SMEM (KV0 + 2 * KVSTG)

__device__ __forceinline__ void attn_issue(uint32_t stg,
    const uint16_t* __restrict__ qkv, int b, int h, int kt, int tid)
{
    #pragma unroll
    for (int i = 0; i < 2; i++) {
        int c = i * 256 + tid;
        int rr = c >> 3, kc = c & 7;
        size_t base = (size_t)(b * SEQ + kt * 64 + rr) * H3 + h * HDIM + kc * 8;
        uint32_t doff = (uint32_t)(rr * AROW + kc * 16);
        cpa16(stg + doff,        qkv + base + E);
        cpa16(stg + 9216 + doff, qkv + base + 2 * E);
    }
    CP_COMMIT();
}

__global__ __launch_bounds__(256, 2)
void attn_mma(const uint16_t* __restrict__ qkv, uint16_t* __restrict__ out)
{
    extern __shared__ char sm[];
    uint32_t sb = smem_u32(sm);
    int qt = blockIdx.x, h = blockIdx.y, b = blockIdx.z;
    int tid = threadIdx.x, w = tid >> 5, lane = tid & 31;
    int g = lane >> 2, tig = lane & 3;

    #pragma unroll
    for (int i = 0; i < 4; i++) {
        int idx = i * 256 + tid;
        int r = idx >> 3, kc = idx & 7;
        size_t t = (size_t)(b * SEQ + qt * 128 + r) * H3 + h * HDIM + kc * 8;
        cpa16(sb + (uint32_t)(r * AROW + kc * 16), qkv + t);
    }
    CP_COMMIT();
    attn_issue(sb + KV0, qkv, b, h, 0, tid);
    CP_WAIT0();
    __syncthreads();

    uint32_t qh[4][4];
    {
        uint32_t qa = sb + (uint32_t)(w * 16 + (lane & 15)) * AROW
                    + ((lane >> 4) * 8) * 2;
        #pragma unroll
        for (int ks = 0; ks < 4; ks++)
            LDSM_X4(qh[ks], qa + (uint32_t)(ks * 32));
    }

    float o[8][4];
    #pragma unroll
    for (int nf = 0; nf < 8; nf++)
        #pragma unroll
        for (int c = 0; c < 4; c++) o[nf][c] = 0.f;
    float m_[2] = {-1e30f, -1e30f};
    float l_[2] = {0.f, 0.f};

    uint32_t kb_off = (uint32_t)((lane & 7) + ((lane >> 4) & 1) * 8) * AROW
                    + (((lane >> 3) & 1) * 8) * 2;
    uint32_t vb_off = (uint32_t)(lane & 15) * AROW + ((lane >> 4) * 8) * 2 + 9216;

    for (int kt = 0; kt < SEQ / 64; kt++) {
        uint32_t stg = sb + KV0 + (uint32_t)(kt & 1) * KVSTG;

        if (kt + 1 < SEQ / 64)
            attn_issue(sb + KV0 + (uint32_t)((kt + 1) & 1) * KVSTG,
                       qkv, b, h, kt + 1, tid);

        float s[8][4];
        #pragma unroll
        for (int nf = 0; nf < 8; nf++)
            #pragma unroll
            for (int c = 0; c < 4; c++) s[nf][c] = 0.f;

        #pragma unroll
        for (int ks = 0; ks < 4; ks++) {
            uint32_t koff = (uint32_t)(ks * 32);
            #pragma unroll
            for (int ng = 0; ng < 4; ng++) {
                uint32_t kh[4];
                LDSM_X4(kh, stg + kb_off + (uint32_t)(ng * 16) * AROW + koff);
                #pragma unroll
                for (int j = 0; j < 2; j++)
                    mma_f16(s[ng * 2 + j], qh[ks], &kh[j * 2]);
            }
        }

        #pragma unroll
        for (int hh = 0; hh < 2; hh++) {
            float mx = s[0][hh * 2];
            #pragma unroll
            for (int nf = 0; nf < 8; nf++) {
                mx = fmaxf(mx, s[nf][hh * 2 + 0]);
                mx = fmaxf(mx, s[nf][hh * 2 + 1]);
            }
            mx = fmaxf(mx, __shfl_xor_sync(0xffffffffu, mx, 1));
            mx = fmaxf(mx, __shfl_xor_sync(0xffffffffu, mx, 2));
            float mn = fmaxf(m_[hh], mx);
            float alpha = ex2(m_[hh] - mn);
            m_[hh] = mn;
            float lsum = 0.f;
            #pragma unroll
            for (int nf = 0; nf < 8; nf++) {
                float p0 = ex2(s[nf][hh * 2 + 0] - mn);
                float p1 = ex2(s[nf][hh * 2 + 1] - mn);
                s[nf][hh * 2 + 0] = p0;
                s[nf][hh * 2 + 1] = p1;
                lsum += p0 + p1;
                o[nf][hh * 2 + 0] *= alpha;
                o[nf][hh * 2 + 1] *= alpha;
            }
            l_[hh] = l_[hh] * alpha + lsum;
        }

        #pragma unroll
        for (int ks = 0; ks < 4; ks++) {
            uint32_t ph[4];
            ph[0] = pack_f16(s[ks*2  ][0], s[ks*2  ][1]);
            ph[1] = pack_f16(s[ks*2  ][2], s[ks*2  ][3]);
            ph[2] = pack_f16(s[ks*2+1][0], s[ks*2+1][1]);
            ph[3] = pack_f16(s[ks*2+1][2], s[ks*2+1][3]);
            #pragma unroll
            for (int nd = 0; nd < 4; nd++) {
                uint32_t vh[4];
                LDSM_X4_T(vh, stg + vb_off + (uint32_t)(ks * 16) * AROW
                              + (uint32_t)(nd * 16) * 2);
                #pragma unroll
                for (int j = 0; j < 2; j++)
                    mma_f16(o[nd * 2 + j], ph, &vh[j * 2]);
            }
        }

        CP_WAIT0();
        __syncthreads();
    }

    #pragma unroll
    for (int hh = 0; hh < 2; hh++) {
        float lt = l_[hh];
        lt += __shfl_xor_sync(0xffffffffu, lt, 1);
        lt += __shfl_xor_sync(0xffffffffu, lt, 2);
        float inv = 1.0f / lt;
        int row = qt * 128 + w * 16 + g + hh * 8;
        size_t base = (size_t)(b * SEQ + row) * E + h * HDIM;
        #pragma unroll
        for (int nf = 0; nf < 8; nf++) {
            int col = nf * 8 + tig * 2;
            *(uint32_t*)(out + base + col) =
                pack_f16(o[nf][hh * 2 + 0] * inv, o[nf][hh * 2 + 1] * inv);
        }
    }
}

// ---------------------------------------------------------------------------
// Launch
// ---------------------------------------------------------------------------
extern "C" void kernel_launch(void* const* d_in, const int* in_sizes, int n_in,
                              void* d_out, int out_size)
{
    const float* x     = (const float*)d_in[0];
    const float* qkv_w = (const float*)d_in[1];
    const float* fc_w  = (const float*)d_in[2];
    const float* fc_b  = (const float*)d_in[3];
    const float* ln1_g = (const float*)d_in[4];
    const float* ln1_b = (const float*)d_in[5];
    const float* ln2_g = (const float*)d_in[6];
    const float* ln2_b = (const float*)d_in[7];
    const float* w1    = (const float*)d_in[8];
    const float* b1    = (const float*)d_in[9];
    const float* w2    = (const float*)d_in[10];
    const float* b2    = (const float*)d_in[11];
    float* out = (float*)d_out;

    uint16_t *ph, *pqkv, *pattn, *pmlp, *wq, *wf, *ww1, *ww2;
    float* px1;
    cudaGetSymbolAddress((void**)&ph,    g_h);
    cudaGetSymbolAddress((void**)&pqkv,  g_qkv);
    cudaGetSymbolAddress((void**)&pattn, g_attn);
    cudaGetSymbolAddress((void**)&pmlp,  g_mlp);
    cudaGetSymbolAddress((void**)&px1,   g_x1);
    cudaGetSymbolAddress((void**)&wq,    g_wq);
    cudaGetSymbolAddress((void**)&wf,    g_wf);
    cudaGetSymbolAddress((void**)&ww1,   g_w1);
    cudaGetSymbolAddress((void**)&ww2,   g_w2);

    cudaFuncSetAttribute(gemm_mma, cudaFuncAttributeMaxDynamicSharedMemorySize,
                         GEMM_SMEM);
    cudaFuncSetAttribute(attn_mma, cudaFuncAttributeMaxDynamicSharedMemorySize,
                         ATTN_SMEM);

    wconv<<<(H3 * E / 4 + 255) / 256, 256>>>(qkv_w, wq, H3 * E / 4);
    wconv<<<(E * E / 4 + 255) / 256, 256>>>(fc_w, wf, E * E / 4);
    wconv<<<(MLPD * E / 4 + 255) / 256, 256>>>(w1, ww1, MLPD * E / 4);
    wconv<<<(E * MLPD / 4 + 255) / 256, 256>>>(w2, ww2, E * MLPD / 4);

    ln_kernel<<<TOK, 256>>>(x, ln1_g, ln1_b, ph);
    gemm_mma<<<dim3(H3 / 128, TOK / 128), 128, GEMM_SMEM>>>(
        ph, wq, nullptr, nullptr, nullptr, pqkv, TOK, H3, E, 0, E);
    attn_mma<<<dim3(SEQ / 128, NHEAD, 4), 256, ATTN_SMEM>>>(pqkv, pattn);
    gemm_mma<<<dim3(E / 128, TOK / 128), 128, GEMM_SMEM>>>(
        pattn, wf, fc_b, x, px1, nullptr, TOK, E, E, 0, 0);
    ln_kernel<<<TOK, 256>>>(px1, ln2_g, ln2_b, ph);
    gemm_mma<<<dim3(MLPD / 128, TOK / 128), 128, GEMM_SMEM>>>(
        ph, ww1, b1, nullptr, nullptr, pmlp, TOK, MLPD, E, 1, 0);
    gemm_mma<<<dim3(E / 128, TOK / 128), 128, GEMM_SMEM>>>(
        pmlp, ww2, b2, px1, out, nullptr, TOK, E, MLPD, 0, 0);
}

// round 13
// speedup vs baseline: 3.3602x; 1.0201x over previous
#include <cuda_runtime.h>
#include <cuda_fp16.h>
#include <cstdint>
#include <math.h>

#define TOK   8192
#define E     1024
#define H3    3072
#define MLPD  4096
#define NHEAD 16
#define HDIM  64
#define SEQ   2048

// ---------------------------------------------------------------------------
// Scratch
// ---------------------------------------------------------------------------
__device__ uint16_t g_h   [(size_t)TOK * E];
__device__ uint16_t g_qkv [(size_t)TOK * H3];
__device__ uint16_t g_attn[(size_t)TOK * E];
__device__ float    g_x1  [(size_t)TOK * E];
__device__ uint16_t g_mlp [(size_t)TOK * MLPD];
__device__ uint16_t g_wq  [(size_t)H3 * E];
__device__ uint16_t g_wf  [(size_t)E * E];
__device__ uint16_t g_w1  [(size_t)MLPD * E];
__device__ uint16_t g_w2  [(size_t)E * MLPD];

#define QSCALE 0.18033688011112042f   // 0.125 * log2(e)

__device__ __forceinline__ uint32_t smem_u32(const void* p) {
    uint32_t a;
    asm("{ .reg .u64 t; cvta.to.shared.u64 t, %1; cvt.u32.u64 %0, t; }"
        : "=r"(a) : "l"(p));
    return a;
}

#define LDSM_X4(r, addr) \
    asm volatile("ldmatrix.sync.aligned.m8n8.x4.shared.b16 {%0,%1,%2,%3}, [%4];" \
        : "=r"((r)[0]), "=r"((r)[1]), "=r"((r)[2]), "=r"((r)[3]) : "r"(addr))

#define LDSM_X4_T(r, addr) \
    asm volatile("ldmatrix.sync.aligned.m8n8.x4.trans.shared.b16 {%0,%1,%2,%3}, [%4];" \
        : "=r"((r)[0]), "=r"((r)[1]), "=r"((r)[2]), "=r"((r)[3]) : "r"(addr))

__device__ __forceinline__ void mma_f16(float* c, const uint32_t* a, const uint32_t* b) {
    asm volatile(
        "mma.sync.aligned.m16n8k16.row.col.f32.f16.f16.f32 "
        "{%0,%1,%2,%3}, {%4,%5,%6,%7}, {%8,%9}, {%0,%1,%2,%3};"
        : "+f"(c[0]), "+f"(c[1]), "+f"(c[2]), "+f"(c[3])
        : "r"(a[0]), "r"(a[1]), "r"(a[2]), "r"(a[3]), "r"(b[0]), "r"(b[1]));
}

__device__ __forceinline__ uint32_t pack_f16(float c0, float c1) {
    uint32_t h;
    asm("cvt.rn.f16x2.f32 %0, %1, %2;" : "=r"(h) : "f"(c1), "f"(c0));
    return h;
}

__device__ __forceinline__ float ex2(float x) {
    float r;
    asm("ex2.approx.f32 %0, %1;" : "=f"(r) : "f"(x));
    return r;
}

__device__ __forceinline__ void cpa16(uint32_t dst, const void* src) {
    asm volatile("cp.async.cg.shared.global [%0], [%1], 16;"
                 :: "r"(dst), "l"(src));
}
#define CP_COMMIT() asm volatile("cp.async.commit_group;" ::: "memory")
#define CP_WAIT0()  asm volatile("cp.async.wait_group 0;" ::: "memory")
#define CP_WAIT1()  asm volatile("cp.async.wait_group 1;" ::: "memory")

// ---------------------------------------------------------------------------
// Weight pre-convert fp32 -> fp16
// ---------------------------------------------------------------------------
__global__ void wconv(const float* __restrict__ src, uint16_t* __restrict__ dst,
                      int n4)
{
    int i = blockIdx.x * 256 + threadIdx.x;
    if (i < n4) {
        float4 v = ((const float4*)src)[i];
        ((uint2*)dst)[i] = make_uint2(pack_f16(v.x, v.y), pack_f16(v.z, v.w));
    }
}

// ---------------------------------------------------------------------------
// LayerNorm: fp32 in -> fp16 out
// ---------------------------------------------------------------------------
__global__ void ln_kernel(const float* __restrict__ x,
                          const float* __restrict__ g,
                          const float* __restrict__ b,
                          uint16_t* __restrict__ y)
{
    int row = blockIdx.x;
    int tid = threadIdx.x;
    const float4* xr = (const float4*)(x + (size_t)row * E);
    float4 v = xr[tid];

    float s  = v.x + v.y + v.z + v.w;
    float ss = v.x * v.x + v.y * v.y + v.z * v.z + v.w * v.w;

    __shared__ float sbuf[32], sbuf2[32];
    #pragma unroll
    for (int o = 16; o > 0; o >>= 1) {
        s  += __shfl_down_sync(0xffffffffu, s,  o);
        ss += __shfl_down_sync(0xffffffffu, ss, o);
    }
    int warp = tid >> 5, lane = tid & 31;
    if (lane == 0) { sbuf[warp] = s; sbuf2[warp] = ss; }
    __syncthreads();
    if (warp == 0) {
        s  = lane < 8 ? sbuf[lane]  : 0.f;
        ss = lane < 8 ? sbuf2[lane] : 0.f;
        #pragma unroll
        for (int o = 4; o > 0; o >>= 1) {
            s  += __shfl_down_sync(0xffffffffu, s,  o);
            ss += __shfl_down_sync(0xffffffffu, ss, o);
        }
        if (lane == 0) { sbuf[0] = s; sbuf2[0] = ss; }
    }
    __syncthreads();
    float mean = sbuf[0] * (1.0f / E);
    float var  = sbuf2[0] * (1.0f / E) - mean * mean;
    float rstd = rsqrtf(var + 1e-5f);

    float4 gv = ((const float4*)g)[tid];
    float4 bv = ((const float4*)b)[tid];
    float o0 = (v.x - mean) * rstd * gv.x + bv.x;
    float o1 = (v.y - mean) * rstd * gv.y + bv.y;
    float o2 = (v.z - mean) * rstd * gv.z + bv.z;
    float o3 = (v.w - mean) * rstd * gv.w + bv.w;
    *(uint2*)(y + (size_t)row * E + tid * 4) =
        make_uint2(pack_f16(o0, o1), pack_f16(o2, o3));
}

// ---------------------------------------------------------------------------
// fp16 mma.sync NT GEMM, 3-stage cp.async ring. (unchanged from R12)
// CTA 128x128, BK=32, 4 warps (64x64 each), 128 threads, 2 CTAs/SM.
// ---------------------------------------------------------------------------
#define SROW   80
#define MATB   10240
#define STAGEB 20480
#define GEMM_SMEM (3 * STAGEB)

__device__ __forceinline__ void gemm_issue(uint32_t stg,
    const uint16_t* __restrict__ Ah, const uint16_t* __restrict__ Bh,
    int K, int k0, int tid)
{
    #pragma unroll
    for (int i = 0; i < 4; i++) {
        int c = i * 128 + tid;               // 0..511
        int r = c >> 2, kc = c & 3;
        uint32_t doff = (uint32_t)(r * SROW + kc * 16);
        size_t soff = (size_t)r * K + k0 + kc * 8;
        cpa16(stg + doff,        Ah + soff);
        cpa16(stg + MATB + doff, Bh + soff);
    }
    CP_COMMIT();
}

__global__ __launch_bounds__(128, 2)
void gemm_mma(const uint16_t* __restrict__ A, const uint16_t* __restrict__ B,
              const float* __restrict__ bias, const float* __restrict__ res,
              float* __restrict__ outf, uint16_t* __restrict__ oh,
              int M, int N, int K, int act, int qcols)
{
    extern __shared__ char sm[];
    uint32_t sb = smem_u32(sm);
    int tid = threadIdx.x, w = tid >> 5, lane = tid & 31;
    int wm = w >> 1, wn = w & 1;
    int bn = blockIdx.x, bm = blockIdx.y;

    const uint16_t* Ab = A + (size_t)bm * 128 * K;
    const uint16_t* Bb = B + (size_t)bn * 128 * K;
    int nch = K >> 5;

    float acc[4][8][4];
    #pragma unroll
    for (int i = 0; i < 4; i++)
        #pragma unroll
        for (int j = 0; j < 8; j++)
            #pragma unroll
            for (int c = 0; c < 4; c++) acc[i][j][c] = 0.f;

    gemm_issue(sb, Ab, Bb, K, 0, tid);
    if (nch > 1) gemm_issue(sb + STAGEB, Ab, Bb, K, 32, tid);

    uint32_t a_row = (uint32_t)(wm * 64 + (lane & 15)) * SROW + ((lane >> 4) * 8) * 2;
    uint32_t b_row = (uint32_t)(wn * 64 + (lane & 7) + ((lane >> 4) & 1) * 8) * SROW
                   + (((lane >> 3) & 1) * 8) * 2;

    int buf = 0;
    for (int k = 0; k < nch; k++) {
        if (k + 1 < nch) CP_WAIT1(); else CP_WAIT0();
        __syncthreads();
        if (k + 2 < nch) {
            int nb = buf + 2; if (nb >= 3) nb -= 3;
            gemm_issue(sb + (uint32_t)nb * STAGEB, Ab, Bb, K, (k + 2) * 32, tid);
        }

        uint32_t stg = sb + (uint32_t)buf * STAGEB;
        #pragma unroll
        for (int ks = 0; ks < 2; ks++) {
            uint32_t koff = (uint32_t)(ks * 32);
            uint32_t ah[4][4], bh[4][4];
            #pragma unroll
            for (int mf = 0; mf < 4; mf++)
                LDSM_X4(ah[mf], stg + a_row + (uint32_t)(mf * 16) * SROW + koff);
            #pragma unroll
            for (int np = 0; np < 4; np++)
                LDSM_X4(bh[np], stg + MATB + b_row + (uint32_t)(np * 16) * SROW + koff);
            #pragma unroll
            for (int mf = 0; mf < 4; mf++)
                #pragma unroll
                for (int nf = 0; nf < 8; nf++)
                    mma_f16(acc[mf][nf], ah[mf], &bh[nf >> 1][(nf & 1) * 2]);
        }
        if (++buf == 3) buf = 0;
    }

    int g = lane >> 2, tig = lane & 3;
    #pragma unroll
    for (int mf = 0; mf < 4; mf++) {
        #pragma unroll
        for (int h2 = 0; h2 < 2; h2++) {
            int row = bm * 128 + wm * 64 + mf * 16 + g + h2 * 8;
            size_t rb = (size_t)row * N;
            #pragma unroll
            for (int nf = 0; nf < 8; nf++) {
                int col = bn * 128 + wn * 64 + nf * 8 + tig * 2;
                float v0 = acc[mf][nf][h2 * 2 + 0];
                float v1 = acc[mf][nf][h2 * 2 + 1];
                if (bias) {
                    float2 bv = *(const float2*)(bias + col);
                    v0 += bv.x; v1 += bv.y;
                }
                if (act == 1) {
                    v0 = 0.5f * v0 * (1.0f + erff(v0 * 0.70710678118654752f));
                    v1 = 0.5f * v1 * (1.0f + erff(v1 * 0.70710678118654752f));
                }
                if (res) {
                    float2 rv = *(const float2*)(res + rb + col);
                    v0 += rv.x; v1 += rv.y;
                }
                if (outf)
                    *(float2*)(outf + rb + col) = make_float2(v0, v1);
                if (oh) {
                    float s0 = v0, s1 = v1;
                    if (col < qcols) { s0 *= QSCALE; s1 *= QSCALE; }
                    *(uint32_t*)(oh + rb + col) = pack_f16(s0, s1);
                }
            }
        }
    }
}

// ---------------------------------------------------------------------------
// fp16 flash attention: 4 warps x 32 Q rows (2 M-fragments share K/V LDSM).
// CTA: 128 Q rows x (head,batch). 128 threads, 2 CTAs/SM. KV tiles 64.
// ---------------------------------------------------------------------------
#define AROW 144
#define KV0  18432
#define KVSTG 18432
#define ATTN_SMEM (KV0 + 2 * KVSTG)

__device__ __forceinline__ void attn_issue(uint32_t stg,
    const uint16_t* __restrict__ qkv, int b, int h, int kt, int tid)
{
    #pragma unroll
    for (int i = 0; i < 4; i++) {
        int c = i * 128 + tid;                // 0..511
        int rr = c >> 3, kc = c & 7;
        size_t base = (size_t)(b * SEQ + kt * 64 + rr) * H3 + h * HDIM + kc * 8;
        uint32_t doff = (uint32_t)(rr * AROW + kc * 16);
        cpa16(stg + doff,        qkv + base + E);
        cpa16(stg + 9216 + doff, qkv + base + 2 * E);
    }
    CP_COMMIT();
}

__global__ __launch_bounds__(128, 2)
void attn_mma(const uint16_t* __restrict__ qkv, uint16_t* __restrict__ out)
{
    extern __shared__ char sm[];
    uint32_t sb = smem_u32(sm);
    int qt = blockIdx.x, h = blockIdx.y, b = blockIdx.z;
    int tid = threadIdx.x, w = tid >> 5, lane = tid & 31;
    int g = lane >> 2, tig = lane & 3;

    // Q tile: 128 rows x 8 chunks of 16B = 1024 chunks over 128 threads
    #pragma unroll
    for (int i = 0; i < 8; i++) {
        int idx = i * 128 + tid;
        int r = idx >> 3, kc = idx & 7;
        size_t t = (size_t)(b * SEQ + qt * 128 + r) * H3 + h * HDIM + kc * 8;
        cpa16(sb + (uint32_t)(r * AROW + kc * 16), qkv + t);
    }
    CP_COMMIT();
    attn_issue(sb + KV0, qkv, b, h, 0, tid);
    CP_WAIT0();
    __syncthreads();

    // preload Q fragments: 2 M-fragments x 4 k-steps
    uint32_t qh[2][4][4];
    #pragma unroll
    for (int mf = 0; mf < 2; mf++) {
        uint32_t qa = sb + (uint32_t)(w * 32 + mf * 16 + (lane & 15)) * AROW
                    + ((lane >> 4) * 8) * 2;
        #pragma unroll
        for (int ks = 0; ks < 4; ks++)
            LDSM_X4(qh[mf][ks], qa + (uint32_t)(ks * 32));
    }

    float o[2][8][4];
    #pragma unroll
    for (int mf = 0; mf < 2; mf++)
        #pragma unroll
        for (int nf = 0; nf < 8; nf++)
            #pragma unroll
            for (int c = 0; c < 4; c++) o[mf][nf][c] = 0.f;
    float m_[2][2] = {{-1e30f, -1e30f}, {-1e30f, -1e30f}};
    float l_[2][2] = {{0.f, 0.f}, {0.f, 0.f}};

    uint32_t kb_off = (uint32_t)((lane & 7) + ((lane >> 4) & 1) * 8) * AROW
                    + (((lane >> 3) & 1) * 8) * 2;
    uint32_t vb_off = (uint32_t)(lane & 15) * AROW + ((lane >> 4) * 8) * 2 + 9216;

    for (int kt = 0; kt < SEQ / 64; kt++) {
        uint32_t stg = sb + KV0 + (uint32_t)(kt & 1) * KVSTG;

        if (kt + 1 < SEQ / 64)
            attn_issue(sb + KV0 + (uint32_t)((kt + 1) & 1) * KVSTG,
                       qkv, b, h, kt + 1, tid);

        // ---- S = Q K^T : K fragments shared across both M-fragments ----
        float s[2][8][4];
        #pragma unroll
        for (int mf = 0; mf < 2; mf++)
            #pragma unroll
            for (int nf = 0; nf < 8; nf++)
                #pragma unroll
                for (int c = 0; c < 4; c++) s[mf][nf][c] = 0.f;

        #pragma unroll
        for (int ks = 0; ks < 4; ks++) {
            uint32_t koff = (uint32_t)(ks * 32);
            #pragma unroll
            for (int ng = 0; ng < 4; ng++) {
                uint32_t kh[4];
                LDSM_X4(kh, stg + kb_off + (uint32_t)(ng * 16) * AROW + koff);
                #pragma unroll
                for (int j = 0; j < 2; j++) {
                    int nf = ng * 2 + j;
                    mma_f16(s[0][nf], qh[0][ks], &kh[j * 2]);
                    mma_f16(s[1][nf], qh[1][ks], &kh[j * 2]);
                }
            }
        }

        // ---- online softmax (base 2) ----
        #pragma unroll
        for (int mf = 0; mf < 2; mf++)
            #pragma unroll
            for (int hh = 0; hh < 2; hh++) {
                float mx = s[mf][0][hh * 2];
                #pragma unroll
                for (int nf = 0; nf < 8; nf++) {
                    mx = fmaxf(mx, s[mf][nf][hh * 2 + 0]);
                    mx = fmaxf(mx, s[mf][nf][hh * 2 + 1]);
                }
                mx = fmaxf(mx, __shfl_xor_sync(0xffffffffu, mx, 1));
                mx = fmaxf(mx, __shfl_xor_sync(0xffffffffu, mx, 2));
                float mn = fmaxf(m_[mf][hh], mx);
                float alpha = ex2(m_[mf][hh] - mn);
                m_[mf][hh] = mn;
                float lsum = 0.f;
                #pragma unroll
                for (int nf = 0; nf < 8; nf++) {
                    float p0 = ex2(s[mf][nf][hh * 2 + 0] - mn);
                    float p1 = ex2(s[mf][nf][hh * 2 + 1] - mn);
                    s[mf][nf][hh * 2 + 0] = p0;
                    s[mf][nf][hh * 2 + 1] = p1;
                    lsum += p0 + p1;
                    o[mf][nf][hh * 2 + 0] *= alpha;
                    o[mf][nf][hh * 2 + 1] *= alpha;
                }
                l_[mf][hh] = l_[mf][hh] * alpha + lsum;
            }

        // ---- O += P V : V fragments shared across both M-fragments ----
        #pragma unroll
        for (int ks = 0; ks < 4; ks++) {
            uint32_t ph[2][4];
            #pragma unroll
            for (int mf = 0; mf < 2; mf++) {
                ph[mf][0] = pack_f16(s[mf][ks*2  ][0], s[mf][ks*2  ][1]);
                ph[mf][1] = pack_f16(s[mf][ks*2  ][2], s[mf][ks*2  ][3]);
                ph[mf][2] = pack_f16(s[mf][ks*2+1][0], s[mf][ks*2+1][1]);
                ph[mf][3] = pack_f16(s[mf][ks*2+1][2], s[mf][ks*2+1][3]);
            }
            #pragma unroll
            for (int nd = 0; nd < 4; nd++) {
                uint32_t vh[4];
                LDSM_X4_T(vh, stg + vb_off + (uint32_t)(ks * 16) * AROW
                              + (uint32_t)(nd * 16) * 2);
                #pragma unroll
                for (int j = 0; j < 2; j++) {
                    int nf = nd * 2 + j;
                    mma_f16(o[0][nf], ph[0], &vh[j * 2]);
                    mma_f16(o[1][nf], ph[1], &vh[j * 2]);
                }
            }
        }

        CP_WAIT0();
        __syncthreads();
    }

    // ---- finalize ----
    #pragma unroll
    for (int mf = 0; mf < 2; mf++)
        #pragma unroll
        for (int hh = 0; hh < 2; hh++) {
            float lt = l_[mf][hh];
            lt += __shfl_xor_sync(0xffffffffu, lt, 1);
            lt += __shfl_xor_sync(0xffffffffu, lt, 2);
            float inv = 1.0f / lt;
            int row = qt * 128 + w * 32 + mf * 16 + g + hh * 8;
            size_t base = (size_t)(b * SEQ + row) * E + h * HDIM;
            #pragma unroll
            for (int nf = 0; nf < 8; nf++) {
                int col = nf * 8 + tig * 2;
                *(uint32_t*)(out + base + col) =
                    pack_f16(o[mf][nf][hh * 2 + 0] * inv,
                             o[mf][nf][hh * 2 + 1] * inv);
            }
        }
}

// ---------------------------------------------------------------------------
// Launch
// ---------------------------------------------------------------------------
extern "C" void kernel_launch(void* const* d_in, const int* in_sizes, int n_in,
                              void* d_out, int out_size)
{
    const float* x     = (const float*)d_in[0];
    const float* qkv_w = (const float*)d_in[1];
    const float* fc_w  = (const float*)d_in[2];
    const float* fc_b  = (const float*)d_in[3];
    const float* ln1_g = (const float*)d_in[4];
    const float* ln1_b = (const float*)d_in[5];
    const float* ln2_g = (const float*)d_in[6];
    const float* ln2_b = (const float*)d_in[7];
    const float* w1    = (const float*)d_in[8];
    const float* b1    = (const float*)d_in[9];
    const float* w2    = (const float*)d_in[10];
    const float* b2    = (const float*)d_in[11];
    float* out = (float*)d_out;

    uint16_t *ph, *pqkv, *pattn, *pmlp, *wq, *wf, *ww1, *ww2;
    float* px1;
    cudaGetSymbolAddress((void**)&ph,    g_h);
    cudaGetSymbolAddress((void**)&pqkv,  g_qkv);
    cudaGetSymbolAddress((void**)&pattn, g_attn);
    cudaGetSymbolAddress((void**)&pmlp,  g_mlp);
    cudaGetSymbolAddress((void**)&px1,   g_x1);
    cudaGetSymbolAddress((void**)&wq,    g_wq);
    cudaGetSymbolAddress((void**)&wf,    g_wf);
    cudaGetSymbolAddress((void**)&ww1,   g_w1);
    cudaGetSymbolAddress((void**)&ww2,   g_w2);

    cudaFuncSetAttribute(gemm_mma, cudaFuncAttributeMaxDynamicSharedMemorySize,
                         GEMM_SMEM);
    cudaFuncSetAttribute(attn_mma, cudaFuncAttributeMaxDynamicSharedMemorySize,
                         ATTN_SMEM);

    wconv<<<(H3 * E / 4 + 255) / 256, 256>>>(qkv_w, wq, H3 * E / 4);
    wconv<<<(E * E / 4 + 255) / 256, 256>>>(fc_w, wf, E * E / 4);
    wconv<<<(MLPD * E / 4 + 255) / 256, 256>>>(w1, ww1, MLPD * E / 4);
    wconv<<<(E * MLPD / 4 + 255) / 256, 256>>>(w2, ww2, E * MLPD / 4);

    ln_kernel<<<TOK, 256>>>(x, ln1_g, ln1_b, ph);
    gemm_mma<<<dim3(H3 / 128, TOK / 128), 128, GEMM_SMEM>>>(
        ph, wq, nullptr, nullptr, nullptr, pqkv, TOK, H3, E, 0, E);
    attn_mma<<<dim3(SEQ / 128, NHEAD, 4), 128, ATTN_SMEM>>>(pqkv, pattn);
    gemm_mma<<<dim3(E / 128, TOK / 128), 128, GEMM_SMEM>>>(
        pattn, wf, fc_b, x, px1, nullptr, TOK, E, E, 0, 0);
    ln_kernel<<<TOK, 256>>>(px1, ln2_g, ln2_b, ph);
    gemm_mma<<<dim3(MLPD / 128, TOK / 128), 128, GEMM_SMEM>>>(
        ph, ww1, b1, nullptr, nullptr, pmlp, TOK, MLPD, E, 1, 0);
    gemm_mma<<<dim3(E / 128, TOK / 128), 128, GEMM_SMEM>>>(
        pmlp, ww2, b2, px1, out, nullptr, TOK, E, MLPD, 0, 0);
}